// round 2
// baseline (speedup 1.0000x reference)
#include <cuda_runtime.h>
#include <math.h>
#include <stdint.h>

#define BATCH 8
#define DCH 6
#define NC 48
#define HH 256
#define WWI 256
#define HW 65536            // 256*256
#define H1 258
#define W1S 264
#define CH1SZ (H1*W1S)      // 68112
#define H3 130
#define W3S 132
#define CH3SZ (H3*W3S)      // 17160
#define HWo 16384           // 128*128

// ---------------- scratch (static device memory; no allocations) ----------------
__device__ float g_E[BATCH*HW];                          // 2 MB
__device__ float g_h1[(size_t)BATCH*NC*CH1SZ];           // ~105 MB  tanh(conv1)
__device__ float g_h2[(size_t)BATCH*NC*HW];              // ~101 MB  tanh(conv2)
__device__ float g_cm1[(size_t)BATCH*NC*HWo];            // 25 MB    raw cm conv
__device__ float g_h3[(size_t)BATCH*NC*CH3SZ];           // 26 MB    tanh(conv cm_ct)
__device__ float g_xm[BATCH*DCH*HWo];                    // 3 MB
__device__ float g_chg[BATCH*HWo];                       // 0.5 MB

__device__ double g_S6[2][6];     // 0: x moments, 1: xm moments
__device__ double g_M6[2][21];
__device__ double g_S48[2][48];   // 0: h2, 1: cm1
__device__ double g_SS48[2][48];
__device__ float  g_scale[4][48]; // 0=ce,1=md,2=cm,3=bo
__device__ float  g_shift[4][48];

__device__ const int g_DX[8] = {0,1,1,1,0,-1,-1,-1};
__device__ const int g_DY[8] = {1,1,0,-1,-1,-1,0,1};

// ---------------- zero stats ----------------
__global__ void k_zero() {
    int t = threadIdx.x;
    if (t < 12) (&g_S6[0][0])[t] = 0.0;
    if (t < 42) (&g_M6[0][0])[t] = 0.0;
    if (t < 96) (&g_S48[0][0])[t] = 0.0;
    if (t < 96) (&g_SS48[0][0])[t] = 0.0;
}

// ---------------- 6-channel first/second moments (x or xm) ----------------
__global__ void k_stats6(const float* __restrict__ xin, int which) {
    const float* p = which ? (const float*)g_xm : xin;
    int HWl = which ? HWo : HW;
    double* S = g_S6[which];
    double* M = g_M6[which];
    int total = BATCH*HWl;
    double mu[6]; double mm[21];
#pragma unroll
    for (int d = 0; d < 6; d++) mu[d] = 0.0;
#pragma unroll
    for (int i = 0; i < 21; i++) mm[i] = 0.0;
    for (int idx = blockIdx.x*blockDim.x + threadIdx.x; idx < total;
         idx += gridDim.x*blockDim.x) {
        int b = idx / HWl; int q = idx - b*HWl;
        const float* base = p + (size_t)b*6*HWl + q;
        float v[6];
#pragma unroll
        for (int d = 0; d < 6; d++) v[d] = base[(size_t)d*HWl];
        int t = 0;
#pragma unroll
        for (int d = 0; d < 6; d++) {
            mu[d] += (double)v[d];
#pragma unroll
            for (int e = d; e < 6; e++) { mm[t] += (double)v[d]*(double)v[e]; t++; }
        }
    }
#pragma unroll
    for (int o = 16; o > 0; o >>= 1) {
#pragma unroll
        for (int d = 0; d < 6; d++)  mu[d] += __shfl_down_sync(0xffffffffu, mu[d], o);
#pragma unroll
        for (int i = 0; i < 21; i++) mm[i] += __shfl_down_sync(0xffffffffu, mm[i], o);
    }
    __shared__ double sS[6], sM[21];
    if (threadIdx.x < 6)  sS[threadIdx.x] = 0.0;
    if (threadIdx.x < 21) sM[threadIdx.x] = 0.0;
    __syncthreads();
    if ((threadIdx.x & 31) == 0) {
        for (int d = 0; d < 6; d++)  atomicAdd(&sS[d], mu[d]);
        for (int i = 0; i < 21; i++) atomicAdd(&sM[i], mm[i]);
    }
    __syncthreads();
    if (threadIdx.x < 6)  atomicAdd(&S[threadIdx.x], sS[threadIdx.x]);
    if (threadIdx.x < 21) atomicAdd(&M[threadIdx.x], sM[threadIdx.x]);
}

// ---------------- analytic BN for 1x1 convs (ce / bo) ----------------
__global__ void k_final6(const float* __restrict__ w1, const float* __restrict__ gg,
                         const float* __restrict__ bb, int which, int outi) {
    int c = threadIdx.x; if (c >= 48) return;
    double N = which ? (double)(BATCH*HWo) : (double)(BATCH*HW);
    const double* S = g_S6[which];
    const double* M = g_M6[which];
    double wl[6]; double m = 0.0;
    for (int d = 0; d < 6; d++) { wl[d] = (double)w1[c*6+d]; m += wl[d]*(S[d]/N); }
    double e2 = 0.0; int t = 0;
    for (int d = 0; d < 6; d++)
        for (int e = d; e < 6; e++) {
            double coef = (d == e) ? 1.0 : 2.0;
            e2 += coef*wl[d]*wl[e]*(M[t]/N); t++;
        }
    double var = e2 - m*m;
    if (var < 0.0) var = 0.0;
    double sc = (double)gg[c] / sqrt(var + 1e-5);
    g_scale[outi][c] = (float)sc;
    g_shift[outi][c] = (float)((double)bb[c] - sc*m);
}

// ---------------- per-channel sum/sumsq over 48-ch tensors (h2 / cm1) ----------------
__global__ void k_stats48(int which) {
    const float* p = which ? (const float*)g_cm1 : (const float*)g_h2;
    int HWl = which ? HWo : HW;
    int c = blockIdx.x;
    int total = BATCH*HWl;
    double s = 0.0, ss = 0.0;
    for (int idx = blockIdx.y*blockDim.x + threadIdx.x; idx < total;
         idx += gridDim.y*blockDim.x) {
        int b = idx / HWl; int q = idx - b*HWl;
        float v = p[((size_t)(b*NC + c))*HWl + q];
        s += (double)v; ss += (double)v*(double)v;
    }
#pragma unroll
    for (int o = 16; o > 0; o >>= 1) {
        s  += __shfl_down_sync(0xffffffffu, s, o);
        ss += __shfl_down_sync(0xffffffffu, ss, o);
    }
    __shared__ double sh[2];
    if (threadIdx.x == 0) { sh[0] = 0.0; sh[1] = 0.0; }
    __syncthreads();
    if ((threadIdx.x & 31) == 0) { atomicAdd(&sh[0], s); atomicAdd(&sh[1], ss); }
    __syncthreads();
    if (threadIdx.x == 0) {
        atomicAdd(&g_S48[which][c], sh[0]);
        atomicAdd(&g_SS48[which][c], sh[1]);
    }
}

__global__ void k_final48(const float* __restrict__ gg, const float* __restrict__ bb,
                          int which, int outi, double N) {
    int c = threadIdx.x; if (c >= 48) return;
    double mean = g_S48[which][c]/N;
    double var  = g_SS48[which][c]/N - mean*mean;
    if (var < 0.0) var = 0.0;
    double sc = (double)gg[c] / sqrt(var + 1e-5);
    g_scale[outi][c] = (float)sc;
    g_shift[outi][c] = (float)((double)bb[c] - sc*mean);
}

// ---------------- E map: fused 1x1 conv + analytic BN + tanh + 1x1 conv ----------------
__global__ void k_E(const float* __restrict__ x, const float* __restrict__ w1,
                    const float* __restrict__ w2) {
    __shared__ float sw1[288], sw2[48], ssc[48], ssh[48];
    int t = threadIdx.x;
    for (int i = t; i < 288; i += 256) sw1[i] = w1[i];       // FIX: full 288 load
    if (t < 48) { sw2[t] = w2[t]; ssc[t] = g_scale[0][t]; ssh[t] = g_shift[0][t]; }
    __syncthreads();
    int idx = blockIdx.x*blockDim.x + t;   // 2048*256 = 524288 exactly
    int b = idx >> 16; int q = idx & 65535;
    const float* base = x + (size_t)b*6*HW + q;
    float v0 = base[0], v1 = base[HW], v2 = base[2*HW];
    float v3 = base[3*HW], v4 = base[4*HW], v5 = base[5*HW];
    float sum = 0.f;
#pragma unroll 8
    for (int c = 0; c < 48; c++) {
        const float* w = sw1 + c*6;
        float u = w[0]*v0 + w[1]*v1 + w[2]*v2 + w[3]*v3 + w[4]*v4 + w[5]*v5;
        sum += sw2[c]*tanhf(ssc[c]*u + ssh[c]);
    }
    g_E[idx] = sum;
}

// ---------------- conv1: te(10ch, virtual) -> 48, k3, pad2, out 258x258, tanh ----------------
__global__ void __launch_bounds__(128) k_conv1(const float* __restrict__ x,
                                               const float* __restrict__ wct) {
    __shared__ float s_in[5][34][37];
    __shared__ float s_w[360];
    int b = blockIdx.z / 12, ocg = blockIdx.z % 12, oc0 = ocg*4;
    int r0 = blockIdx.y*32, c0 = blockIdx.x*32;
    for (int i = threadIdx.x; i < 360; i += 128) s_w[i] = wct[oc0*90 + i];
    float acc[4][2][4];
#pragma unroll
    for (int a = 0; a < 4; a++)
#pragma unroll
        for (int r = 0; r < 2; r++)
#pragma unroll
            for (int j = 0; j < 4; j++) acc[a][r][j] = 0.f;
    int tx = threadIdx.x & 7, ty = threadIdx.x >> 3;   // tx 0..7, ty 0..15
    const float* Eb = g_E + (size_t)b*HW;
    for (int ch0 = 0; ch0 < 10; ch0 += 5) {
        __syncthreads();
        for (int i = threadIdx.x; i < 5*1156; i += 128) {
            int c = i / 1156; int r2 = i - c*1156;
            int rr = r2 / 34, cc = r2 - rr*34;
            int hi = r0 - 2 + rr, wi = c0 - 2 + cc;
            float v = 0.f;
            int cg = ch0 + c;
            if ((unsigned)hi < 256u && (unsigned)wi < 256u) {
                if (cg < 2) v = x[((size_t)(b*6 + cg))*HW + hi*256 + wi];
                else {
                    int k = cg - 2;
                    int hh = (hi + g_DY[k]) & 255;
                    int wz = (wi - g_DX[k]) & 255;
                    v = Eb[hh*256 + wz];
                }
            }
            s_in[c][rr][cc] = v;
        }
        __syncthreads();
#pragma unroll
        for (int c = 0; c < 5; c++) {
            int cg = ch0 + c;
#pragma unroll
            for (int kh = 0; kh < 3; kh++) {
                float a6[6], b6[6];
#pragma unroll
                for (int q = 0; q < 6; q++) {
                    a6[q] = s_in[c][ty + kh][4*tx + q];
                    b6[q] = s_in[c][ty + 16 + kh][4*tx + q];
                }
#pragma unroll
                for (int oc = 0; oc < 4; oc++) {
                    int wb = (oc*10 + cg)*9 + kh*3;
                    float w0 = s_w[wb], w1v = s_w[wb+1], w2v = s_w[wb+2];
#pragma unroll
                    for (int jj = 0; jj < 4; jj++) {
                        acc[oc][0][jj] += w0*a6[jj] + w1v*a6[jj+1] + w2v*a6[jj+2];
                        acc[oc][1][jj] += w0*b6[jj] + w1v*b6[jj+1] + w2v*b6[jj+2];
                    }
                }
            }
        }
    }
#pragma unroll
    for (int oc = 0; oc < 4; oc++) {
        size_t base = ((size_t)(b*NC + oc0 + oc))*CH1SZ;
#pragma unroll
        for (int rsel = 0; rsel < 2; rsel++) {
            int orow = r0 + ty + rsel*16;
            if (orow >= H1) continue;
#pragma unroll
            for (int jj = 0; jj < 4; jj++) {
                int ocol = c0 + 4*tx + jj;
                if (ocol < H1)
                    g_h1[base + (size_t)orow*W1S + ocol] = tanhf(acc[oc][rsel][jj]);
            }
        }
    }
}

// ---------------- conv2: 48 -> 48, k3, 256x256 out, tanh (dominant kernel) ----------------
__global__ void __launch_bounds__(128) k_conv2(const float* __restrict__ wc1) {
    __shared__ float s_in[8][34][37];
    __shared__ float s_w[1728];
    int b = blockIdx.z / 12, ocg = blockIdx.z % 12, oc0 = ocg*4;
    int r0 = blockIdx.y*32, c0 = blockIdx.x*32;
    for (int i = threadIdx.x; i < 1728; i += 128) s_w[i] = wc1[oc0*432 + i];
    float acc[4][2][4];
#pragma unroll
    for (int a = 0; a < 4; a++)
#pragma unroll
        for (int r = 0; r < 2; r++)
#pragma unroll
            for (int j = 0; j < 4; j++) acc[a][r][j] = 0.f;
    int tx = threadIdx.x & 7, ty = threadIdx.x >> 3;
    const float* h1b = g_h1 + (size_t)b*NC*CH1SZ;
    for (int ch0 = 0; ch0 < 48; ch0 += 8) {
        __syncthreads();
        for (int i = threadIdx.x; i < 8*1156; i += 128) {
            int c = i / 1156; int r2 = i - c*1156;
            int rr = r2 / 34, cc = r2 - rr*34;
            s_in[c][rr][cc] = h1b[(size_t)(ch0 + c)*CH1SZ + (size_t)(r0 + rr)*W1S + (c0 + cc)];
        }
        __syncthreads();
#pragma unroll
        for (int c = 0; c < 8; c++) {
#pragma unroll
            for (int kh = 0; kh < 3; kh++) {
                float a6[6], b6[6];
#pragma unroll
                for (int q = 0; q < 6; q++) {
                    a6[q] = s_in[c][ty + kh][4*tx + q];
                    b6[q] = s_in[c][ty + 16 + kh][4*tx + q];
                }
#pragma unroll
                for (int oc = 0; oc < 4; oc++) {
                    int wb = (oc*48 + ch0 + c)*9 + kh*3;
                    float w0 = s_w[wb], w1v = s_w[wb+1], w2v = s_w[wb+2];
#pragma unroll
                    for (int jj = 0; jj < 4; jj++) {
                        acc[oc][0][jj] += w0*a6[jj] + w1v*a6[jj+1] + w2v*a6[jj+2];
                        acc[oc][1][jj] += w0*b6[jj] + w1v*b6[jj+1] + w2v*b6[jj+2];
                    }
                }
            }
        }
    }
#pragma unroll
    for (int oc = 0; oc < 4; oc++) {
        size_t base = ((size_t)(b*NC + oc0 + oc))*HW;
#pragma unroll
        for (int rsel = 0; rsel < 2; rsel++) {
            int orow = r0 + ty + rsel*16;
#pragma unroll
            for (int jj = 0; jj < 4; jj++)
                g_h2[base + (size_t)orow*256 + (c0 + 4*tx + jj)] = tanhf(acc[oc][rsel][jj]);
        }
    }
}

// ---------------- CHANGE: bn+tanh(h2) -> k2 s2 conv -> sigmoid ----------------
__global__ void k_change(const float* __restrict__ w2) {
    __shared__ float ssc[48], ssh[48], sw[192];
    int t = threadIdx.x;
    if (t < 48)  { ssc[t] = g_scale[1][t]; ssh[t] = g_shift[1][t]; }
    if (t < 192) sw[t] = w2[t];
    __syncthreads();
    int idx = blockIdx.x*256 + t;   // 512*256 = 131072 exactly
    int b = idx >> 14; int q = idx & 16383;
    int i = q >> 7, j = q & 127;
    const float* h2b = g_h2 + ((size_t)b*NC)*HW + (size_t)(2*i)*256 + 2*j;
    float acc = 0.f;
#pragma unroll 4
    for (int c = 0; c < 48; c++) {
        const float* p = h2b + (size_t)c*HW;
        float sc = ssc[c], sh = ssh[c];
        acc += sw[c*4+0]*tanhf(sc*p[0]   + sh);
        acc += sw[c*4+1]*tanhf(sc*p[1]   + sh);
        acc += sw[c*4+2]*tanhf(sc*p[256] + sh);
        acc += sw[c*4+3]*tanhf(sc*p[257] + sh);
    }
    g_chg[idx] = 1.f/(1.f + expf(-acc));
}

// ---------------- cm1: grouped k2 s2 conv (D->NC, g3) ----------------
__global__ void k_cm1(const float* __restrict__ x, const float* __restrict__ w) {
    int idx = blockIdx.x*blockDim.x + threadIdx.x;
    if (idx >= BATCH*NC*HWo) return;
    int q = idx & 16383; int co = idx >> 14;
    int o = co % 48; int b = co / 48;
    int i = q >> 7, j = q & 127;
    int ic0 = (o >> 4)*2;
    const float* xb = x + ((size_t)(b*6 + ic0))*HW + (size_t)(2*i)*256 + 2*j;
    const float* wp = w + o*8;
    float acc = xb[0]*wp[0] + xb[1]*wp[1] + xb[256]*wp[2] + xb[257]*wp[3]
              + xb[HW]*wp[4] + xb[HW+1]*wp[5] + xb[HW+256]*wp[6] + xb[HW+257]*wp[7];
    g_cm1[idx] = acc;
}

// ---------------- conv cm_ct: bn+tanh(cm1) -> k3 pad2 grouped conv -> tanh, 130x130 ----------------
__global__ void __launch_bounds__(128) k_convcm(const float* __restrict__ wct) {
    __shared__ float s_in[8][34][37];
    __shared__ float s_w[576];
    int b = blockIdx.z / 12, ocg = blockIdx.z % 12, oc0 = ocg*4;
    int icb = (oc0 >> 4)*16;
    int r0 = blockIdx.y*32, c0 = blockIdx.x*32;
    for (int i = threadIdx.x; i < 576; i += 128) s_w[i] = wct[oc0*144 + i];
    float acc[4][2][4];
#pragma unroll
    for (int a = 0; a < 4; a++)
#pragma unroll
        for (int r = 0; r < 2; r++)
#pragma unroll
            for (int j = 0; j < 4; j++) acc[a][r][j] = 0.f;
    int tx = threadIdx.x & 7, ty = threadIdx.x >> 3;
    for (int ch0 = 0; ch0 < 16; ch0 += 8) {
        __syncthreads();
        for (int i = threadIdx.x; i < 8*1156; i += 128) {
            int c = i / 1156; int r2 = i - c*1156;
            int rr = r2 / 34, cc = r2 - rr*34;
            int hi = r0 - 2 + rr, wi = c0 - 2 + cc;
            float v = 0.f;
            int cg = icb + ch0 + c;
            if ((unsigned)hi < 128u && (unsigned)wi < 128u) {
                float raw = g_cm1[((size_t)(b*NC + cg))*HWo + hi*128 + wi];
                v = tanhf(g_scale[2][cg]*raw + g_shift[2][cg]);
            }
            s_in[c][rr][cc] = v;
        }
        __syncthreads();
#pragma unroll
        for (int c = 0; c < 8; c++) {
#pragma unroll
            for (int kh = 0; kh < 3; kh++) {
                float a6[6], b6[6];
#pragma unroll
                for (int q = 0; q < 6; q++) {
                    a6[q] = s_in[c][ty + kh][4*tx + q];
                    b6[q] = s_in[c][ty + 16 + kh][4*tx + q];
                }
#pragma unroll
                for (int oc = 0; oc < 4; oc++) {
                    int wb = (oc*16 + ch0 + c)*9 + kh*3;
                    float w0 = s_w[wb], w1v = s_w[wb+1], w2v = s_w[wb+2];
#pragma unroll
                    for (int jj = 0; jj < 4; jj++) {
                        acc[oc][0][jj] += w0*a6[jj] + w1v*a6[jj+1] + w2v*a6[jj+2];
                        acc[oc][1][jj] += w0*b6[jj] + w1v*b6[jj+1] + w2v*b6[jj+2];
                    }
                }
            }
        }
    }
#pragma unroll
    for (int oc = 0; oc < 4; oc++) {
        size_t base = ((size_t)(b*NC + oc0 + oc))*CH3SZ;
#pragma unroll
        for (int rsel = 0; rsel < 2; rsel++) {
            int orow = r0 + ty + rsel*16;
            if (orow >= H3) continue;
#pragma unroll
            for (int jj = 0; jj < 4; jj++) {
                int ocol = c0 + 4*tx + jj;
                if (ocol < H3)
                    g_h3[base + (size_t)orow*W3S + ocol] = tanhf(acc[oc][rsel][jj]);
            }
        }
    }
}

// ---------------- xm: k3 grouped conv (NC->D, g3), out 128x128, tanh ----------------
__global__ void __launch_bounds__(128) k_convxm(const float* __restrict__ wc2) {
    __shared__ float s_in[8][34][37];
    __shared__ float s_w[288];
    int b = blockIdx.z / 3, g = blockIdx.z % 3;
    int r0 = blockIdx.y*32, c0 = blockIdx.x*32;
    for (int i = threadIdx.x; i < 288; i += 128) s_w[i] = wc2[g*288 + i];
    float acc[2][2][4];
#pragma unroll
    for (int a = 0; a < 2; a++)
#pragma unroll
        for (int r = 0; r < 2; r++)
#pragma unroll
            for (int j = 0; j < 4; j++) acc[a][r][j] = 0.f;
    int tx = threadIdx.x & 7, ty = threadIdx.x >> 3;
    for (int ch0 = 0; ch0 < 16; ch0 += 8) {
        __syncthreads();
        for (int i = threadIdx.x; i < 8*1156; i += 128) {
            int c = i / 1156; int r2 = i - c*1156;
            int rr = r2 / 34, cc = r2 - rr*34;
            s_in[c][rr][cc] = g_h3[((size_t)(b*NC + g*16 + ch0 + c))*CH3SZ
                                   + (size_t)(r0 + rr)*W3S + (c0 + cc)];
        }
        __syncthreads();
#pragma unroll
        for (int c = 0; c < 8; c++) {
#pragma unroll
            for (int kh = 0; kh < 3; kh++) {
                float a6[6], b6[6];
#pragma unroll
                for (int q = 0; q < 6; q++) {
                    a6[q] = s_in[c][ty + kh][4*tx + q];
                    b6[q] = s_in[c][ty + 16 + kh][4*tx + q];
                }
#pragma unroll
                for (int oc = 0; oc < 2; oc++) {
                    int wb = (oc*16 + ch0 + c)*9 + kh*3;
                    float w0 = s_w[wb], w1v = s_w[wb+1], w2v = s_w[wb+2];
#pragma unroll
                    for (int jj = 0; jj < 4; jj++) {
                        acc[oc][0][jj] += w0*a6[jj] + w1v*a6[jj+1] + w2v*a6[jj+2];
                        acc[oc][1][jj] += w0*b6[jj] + w1v*b6[jj+1] + w2v*b6[jj+2];
                    }
                }
            }
        }
    }
#pragma unroll
    for (int oc = 0; oc < 2; oc++) {
        size_t base = ((size_t)(b*6 + g*2 + oc))*HWo;
#pragma unroll
        for (int rsel = 0; rsel < 2; rsel++) {
            int orow = r0 + ty + rsel*16;
#pragma unroll
            for (int jj = 0; jj < 4; jj++)
                g_xm[base + (size_t)orow*128 + (c0 + 4*tx + jj)] = tanhf(acc[oc][rsel][jj]);
        }
    }
}

// ---------------- final: born (fused 1x1/BN/tanh/1x1) + blend + partial sigmoid ----------------
__global__ void k_final(const float* __restrict__ w1, const float* __restrict__ w2,
                        float* __restrict__ out) {
    __shared__ float sw1[288], sw2[288], ssc[48], ssh[48];
    int t = threadIdx.x;
    for (int i = t; i < 288; i += 256) { sw1[i] = w1[i]; sw2[i] = w2[i]; }  // FIX: full 288 load
    if (t < 48)  { ssc[t] = g_scale[3][t]; ssh[t] = g_shift[3][t]; }
    __syncthreads();
    int idx = blockIdx.x*256 + t;    // 512*256 = 131072 exactly
    int b = idx >> 14; int q = idx & 16383;
    const float* xb = g_xm + (size_t)b*6*HWo + q;
    float v[6];
#pragma unroll
    for (int d = 0; d < 6; d++) v[d] = xb[(size_t)d*HWo];
    float bo[6] = {0.f,0.f,0.f,0.f,0.f,0.f};
#pragma unroll 8
    for (int c = 0; c < 48; c++) {
        const float* w = sw1 + c*6;
        float u = w[0]*v[0] + w[1]*v[1] + w[2]*v[2] + w[3]*v[3] + w[4]*v[4] + w[5]*v[5];
        float tv = tanhf(ssc[c]*u + ssh[c]);
#pragma unroll
        for (int d = 0; d < 6; d++) bo[d] += sw2[d*48 + c]*tv;
    }
    float ch = g_chg[idx];
#pragma unroll
    for (int d = 0; d < 6; d++) {
        float r = v[d]*(1.f - ch) + ch*bo[d];
        if (d < 3) r = 1.f/(1.f + expf(-r));
        out[((size_t)(b*6 + d))*HWo + q] = r;
    }
}

// ---------------- launch ----------------
extern "C" void kernel_launch(void* const* d_in, const int* in_sizes, int n_in,
                              void* d_out, int out_size) {
    (void)in_sizes; (void)n_in; (void)out_size;
    const float* x     = (const float*)d_in[0];
    const float* ce_w1 = (const float*)d_in[1];
    const float* ce_g  = (const float*)d_in[2];
    const float* ce_b  = (const float*)d_in[3];
    const float* ce_w2 = (const float*)d_in[4];
    const float* md_ct = (const float*)d_in[5];
    const float* md_c1 = (const float*)d_in[6];
    const float* md_g  = (const float*)d_in[7];
    const float* md_b  = (const float*)d_in[8];
    const float* md_c2 = (const float*)d_in[9];
    const float* cm_w1 = (const float*)d_in[10];
    const float* cm_g  = (const float*)d_in[11];
    const float* cm_b  = (const float*)d_in[12];
    const float* cm_ct = (const float*)d_in[13];
    const float* cm_c2 = (const float*)d_in[14];
    const float* bo_w1 = (const float*)d_in[15];
    const float* bo_g  = (const float*)d_in[16];
    const float* bo_b  = (const float*)d_in[17];
    const float* bo_w2 = (const float*)d_in[18];
    float* out = (float*)d_out;

    k_zero<<<1, 128>>>();

    // compenv branch (shift-invariance collapse)
    k_stats6<<<512, 256>>>(x, 0);
    k_final6<<<1, 64>>>(ce_w1, ce_g, ce_b, 0, 0);
    k_E<<<2048, 256>>>(x, ce_w1, ce_w2);

    // merge determinant branch
    k_conv1<<<dim3(9, 9, 96), 128>>>(x, md_ct);
    k_conv2<<<dim3(8, 8, 96), 128>>>(md_c1);
    k_stats48<<<dim3(48, 32), 256>>>(0);
    k_final48<<<1, 64>>>(md_g, md_b, 0, 1, 524288.0);
    k_change<<<512, 256>>>(md_c2);

    // cell merge branch
    k_cm1<<<(BATCH*NC*HWo + 255)/256, 256>>>(x, cm_w1);
    k_stats48<<<dim3(48, 32), 256>>>(1);
    k_final48<<<1, 64>>>(cm_g, cm_b, 1, 2, 131072.0);
    k_convcm<<<dim3(5, 5, 96), 128>>>(cm_ct);
    k_convxm<<<dim3(4, 4, 24), 128>>>(cm_c2);

    // born + blend
    k_stats6<<<512, 256>>>(x, 1);
    k_final6<<<1, 64>>>(bo_w1, bo_g, bo_b, 1, 3);
    k_final<<<512, 256>>>(bo_w1, bo_w2, out);
}

// round 5
// speedup vs baseline: 1.2614x; 1.2614x over previous
#include <cuda_runtime.h>
#include <math.h>
#include <stdint.h>

#define BATCH 8
#define DCH 6
#define NC 48
#define HW 65536            // 256*256
#define H1 258
#define W1S 264
#define CH1SZ (H1*W1S)      // 68112
#define H3 130
#define W3S 132
#define CH3SZ (H3*W3S)      // 17160
#define HWo 16384           // 128*128

// ---------------- scratch (static device memory; no allocations) ----------------
__device__ float g_E[BATCH*HW];                          // 2 MB
__device__ float g_h1[(size_t)BATCH*NC*CH1SZ];           // ~105 MB  tanh(conv1)
__device__ float g_h2[(size_t)BATCH*NC*HW];              // ~101 MB  tanh(conv2)
__device__ float g_cm1[(size_t)BATCH*NC*HWo];            // 25 MB    raw cm conv
__device__ float g_h3[(size_t)BATCH*NC*CH3SZ];           // 26 MB    tanh(conv cm_ct)
__device__ float g_xm[BATCH*DCH*HWo];                    // 3 MB
__device__ float g_chg[BATCH*HWo];                       // 0.5 MB

__device__ double g_S6[2][6];     // 0: x moments, 1: xm moments
__device__ double g_M6[2][21];
__device__ double g_S48[2][48];   // 0: h2, 1: cm1
__device__ double g_SS48[2][48];
__device__ float  g_scale[4][48]; // 0=ce,1=md,2=cm,3=bo
__device__ float  g_shift[4][48];

__device__ const int g_DX[8] = {0,1,1,1,0,-1,-1,-1};
__device__ const int g_DY[8] = {1,1,0,-1,-1,-1,0,1};

__device__ __forceinline__ void cp_async4(void* sdst, const void* gsrc) {
    unsigned s = (unsigned)__cvta_generic_to_shared(sdst);
    asm volatile("cp.async.ca.shared.global [%0], [%1], 4;\n" :: "r"(s), "l"(gsrc));
}
__device__ __forceinline__ void cp_commit() {
    asm volatile("cp.async.commit_group;\n");
}
__device__ __forceinline__ void cp_wait0() {
    asm volatile("cp.async.wait_group 0;\n");
}

// ---------------- zero stats ----------------
__global__ void k_zero() {
    int t = threadIdx.x;
    if (t < 12) (&g_S6[0][0])[t] = 0.0;
    if (t < 42) (&g_M6[0][0])[t] = 0.0;
    if (t < 96) (&g_S48[0][0])[t] = 0.0;
    if (t < 96) (&g_SS48[0][0])[t] = 0.0;
}

// ---------------- 6-channel first/second moments (x or xm) ----------------
__global__ void k_stats6(const float* __restrict__ xin, int which) {
    const float* p = which ? (const float*)g_xm : xin;
    int HWl = which ? HWo : HW;
    double* S = g_S6[which];
    double* M = g_M6[which];
    int total = BATCH*HWl;
    double mu[6]; double mm[21];
#pragma unroll
    for (int d = 0; d < 6; d++) mu[d] = 0.0;
#pragma unroll
    for (int i = 0; i < 21; i++) mm[i] = 0.0;
    for (int idx = blockIdx.x*blockDim.x + threadIdx.x; idx < total;
         idx += gridDim.x*blockDim.x) {
        int b = idx / HWl; int q = idx - b*HWl;
        const float* base = p + (size_t)b*6*HWl + q;
        float v[6];
#pragma unroll
        for (int d = 0; d < 6; d++) v[d] = base[(size_t)d*HWl];
        int t = 0;
#pragma unroll
        for (int d = 0; d < 6; d++) {
            mu[d] += (double)v[d];
#pragma unroll
            for (int e = d; e < 6; e++) { mm[t] += (double)v[d]*(double)v[e]; t++; }
        }
    }
#pragma unroll
    for (int o = 16; o > 0; o >>= 1) {
#pragma unroll
        for (int d = 0; d < 6; d++)  mu[d] += __shfl_down_sync(0xffffffffu, mu[d], o);
#pragma unroll
        for (int i = 0; i < 21; i++) mm[i] += __shfl_down_sync(0xffffffffu, mm[i], o);
    }
    __shared__ double sS[6], sM[21];
    if (threadIdx.x < 6)  sS[threadIdx.x] = 0.0;
    if (threadIdx.x < 21) sM[threadIdx.x] = 0.0;
    __syncthreads();
    if ((threadIdx.x & 31) == 0) {
        for (int d = 0; d < 6; d++)  atomicAdd(&sS[d], mu[d]);
        for (int i = 0; i < 21; i++) atomicAdd(&sM[i], mm[i]);
    }
    __syncthreads();
    if (threadIdx.x < 6)  atomicAdd(&S[threadIdx.x], sS[threadIdx.x]);
    if (threadIdx.x < 21) atomicAdd(&M[threadIdx.x], sM[threadIdx.x]);
}

// ---------------- analytic BN for 1x1 convs (ce / bo) ----------------
__global__ void k_final6(const float* __restrict__ w1, const float* __restrict__ gg,
                         const float* __restrict__ bb, int which, int outi) {
    int c = threadIdx.x; if (c >= 48) return;
    double N = which ? (double)(BATCH*HWo) : (double)(BATCH*HW);
    const double* S = g_S6[which];
    const double* M = g_M6[which];
    double wl[6]; double m = 0.0;
    for (int d = 0; d < 6; d++) { wl[d] = (double)w1[c*6+d]; m += wl[d]*(S[d]/N); }
    double e2 = 0.0; int t = 0;
    for (int d = 0; d < 6; d++)
        for (int e = d; e < 6; e++) {
            double coef = (d == e) ? 1.0 : 2.0;
            e2 += coef*wl[d]*wl[e]*(M[t]/N); t++;
        }
    double var = e2 - m*m;
    if (var < 0.0) var = 0.0;
    double sc = (double)gg[c] / sqrt(var + 1e-5);
    g_scale[outi][c] = (float)sc;
    g_shift[outi][c] = (float)((double)bb[c] - sc*m);
}

// ---------------- per-channel sum/sumsq over 48-ch tensors (cm1) ----------------
__global__ void k_stats48(int which) {
    const float* p = which ? (const float*)g_cm1 : (const float*)g_h2;
    int HWl = which ? HWo : HW;
    int c = blockIdx.x;
    int total = BATCH*HWl;
    double s = 0.0, ss = 0.0;
    for (int idx = blockIdx.y*blockDim.x + threadIdx.x; idx < total;
         idx += gridDim.y*blockDim.x) {
        int b = idx / HWl; int q = idx - b*HWl;
        float v = p[((size_t)(b*NC + c))*HWl + q];
        s += (double)v; ss += (double)v*(double)v;
    }
#pragma unroll
    for (int o = 16; o > 0; o >>= 1) {
        s  += __shfl_down_sync(0xffffffffu, s, o);
        ss += __shfl_down_sync(0xffffffffu, ss, o);
    }
    __shared__ double sh[2];
    if (threadIdx.x == 0) { sh[0] = 0.0; sh[1] = 0.0; }
    __syncthreads();
    if ((threadIdx.x & 31) == 0) { atomicAdd(&sh[0], s); atomicAdd(&sh[1], ss); }
    __syncthreads();
    if (threadIdx.x == 0) {
        atomicAdd(&g_S48[which][c], sh[0]);
        atomicAdd(&g_SS48[which][c], sh[1]);
    }
}

__global__ void k_final48(const float* __restrict__ gg, const float* __restrict__ bb,
                          int which, int outi, double N) {
    int c = threadIdx.x; if (c >= 48) return;
    double mean = g_S48[which][c]/N;
    double var  = g_SS48[which][c]/N - mean*mean;
    if (var < 0.0) var = 0.0;
    double sc = (double)gg[c] / sqrt(var + 1e-5);
    g_scale[outi][c] = (float)sc;
    g_shift[outi][c] = (float)((double)bb[c] - sc*mean);
}

// ---------------- E map: fused 1x1 conv + analytic BN + tanh + 1x1 conv ----------------
__global__ void k_E(const float* __restrict__ x, const float* __restrict__ w1,
                    const float* __restrict__ w2) {
    __shared__ float sw1[288], sw2[48], ssc[48], ssh[48];
    int t = threadIdx.x;
    for (int i = t; i < 288; i += 256) sw1[i] = w1[i];
    if (t < 48) { sw2[t] = w2[t]; ssc[t] = g_scale[0][t]; ssh[t] = g_shift[0][t]; }
    __syncthreads();
    int idx = blockIdx.x*blockDim.x + t;   // 2048*256 = 524288 exactly
    int b = idx >> 16; int q = idx & 65535;
    const float* base = x + (size_t)b*6*HW + q;
    float v0 = base[0], v1 = base[HW], v2 = base[2*HW];
    float v3 = base[3*HW], v4 = base[4*HW], v5 = base[5*HW];
    float sum = 0.f;
#pragma unroll 8
    for (int c = 0; c < 48; c++) {
        const float* w = sw1 + c*6;
        float u = w[0]*v0 + w[1]*v1 + w[2]*v2 + w[3]*v3 + w[4]*v4 + w[5]*v5;
        sum += sw2[c]*tanhf(ssc[c]*u + ssh[c]);
    }
    g_E[idx] = sum;
}

// ---------------- conv1: te(10ch, virtual) -> 48, k3, pad2, out 258x258, tanh ----------------
// 8 output channels per block
__global__ void __launch_bounds__(128) k_conv1(const float* __restrict__ x,
                                               const float* __restrict__ wct) {
    __shared__ float s_in[5][34*37];
    __shared__ float s_w[720];
    int b = blockIdx.z / 6, ocg = blockIdx.z % 6, oc0 = ocg*8;
    int r0 = blockIdx.y*32, c0 = blockIdx.x*32;
    for (int i = threadIdx.x; i < 720; i += 128) s_w[i] = wct[oc0*90 + i];
    float acc[8][2][4];
#pragma unroll
    for (int a = 0; a < 8; a++)
#pragma unroll
        for (int r = 0; r < 2; r++)
#pragma unroll
            for (int j = 0; j < 4; j++) acc[a][r][j] = 0.f;
    int tx = threadIdx.x & 7, ty = threadIdx.x >> 3;   // tx 0..7, ty 0..15
    const float* Eb = g_E + (size_t)b*HW;
    for (int ch0 = 0; ch0 < 10; ch0 += 5) {
        __syncthreads();
        for (int i = threadIdx.x; i < 5*1156; i += 128) {
            int c = i / 1156; int r2 = i - c*1156;
            int rr = r2 / 34, cc = r2 - rr*34;
            int hi = r0 - 2 + rr, wi = c0 - 2 + cc;
            float v = 0.f;
            int cg = ch0 + c;
            if ((unsigned)hi < 256u && (unsigned)wi < 256u) {
                if (cg < 2) v = x[((size_t)(b*6 + cg))*HW + hi*256 + wi];
                else {
                    int k = cg - 2;
                    int hh = (hi + g_DY[k]) & 255;
                    int wz = (wi - g_DX[k]) & 255;
                    v = Eb[hh*256 + wz];
                }
            }
            s_in[c][rr*37 + cc] = v;
        }
        __syncthreads();
#pragma unroll
        for (int c = 0; c < 5; c++) {
            int cg = ch0 + c;
#pragma unroll
            for (int kh = 0; kh < 3; kh++) {
                float a6[6], b6[6];
#pragma unroll
                for (int q = 0; q < 6; q++) {
                    a6[q] = s_in[c][(ty + kh)*37 + 4*tx + q];
                    b6[q] = s_in[c][(ty + 16 + kh)*37 + 4*tx + q];
                }
#pragma unroll
                for (int oc = 0; oc < 8; oc++) {
                    int wb = oc*90 + cg*9 + kh*3;
                    float w0 = s_w[wb], w1v = s_w[wb+1], w2v = s_w[wb+2];
#pragma unroll
                    for (int jj = 0; jj < 4; jj++) {
                        acc[oc][0][jj] += w0*a6[jj] + w1v*a6[jj+1] + w2v*a6[jj+2];
                        acc[oc][1][jj] += w0*b6[jj] + w1v*b6[jj+1] + w2v*b6[jj+2];
                    }
                }
            }
        }
    }
#pragma unroll
    for (int oc = 0; oc < 8; oc++) {
        size_t base = ((size_t)(b*NC + oc0 + oc))*CH1SZ;
#pragma unroll
        for (int rsel = 0; rsel < 2; rsel++) {
            int orow = r0 + ty + rsel*16;
            if (orow >= H1) continue;
#pragma unroll
            for (int jj = 0; jj < 4; jj++) {
                int ocol = c0 + 4*tx + jj;
                if (ocol < H1)
                    g_h1[base + (size_t)orow*W1S + ocol] = tanhf(acc[oc][rsel][jj]);
            }
        }
    }
}

// ---------------- conv2: 48 -> 48, k3, 256x256 out, tanh (dominant kernel) ----------------
// 8 oc per block, cp.async double-buffered over 16 chunks of 3 input channels,
// fused per-channel sum/sumsq stats (md BN).
#define C2NCH 16
__global__ void __launch_bounds__(128) k_conv2(const float* __restrict__ wc1) {
    __shared__ float s_in[2][3][34*37];
    __shared__ float s_w[8*432];
    __shared__ float s_red[8][4][2];
    int b = blockIdx.z / 6, ocg = blockIdx.z % 6, oc0 = ocg*8;
    int r0 = blockIdx.y*32, c0 = blockIdx.x*32;
    for (int i = threadIdx.x; i < 8*432; i += 128) s_w[i] = wc1[oc0*432 + i];
    float acc[8][2][4];
#pragma unroll
    for (int a = 0; a < 8; a++)
#pragma unroll
        for (int r = 0; r < 2; r++)
#pragma unroll
            for (int j = 0; j < 4; j++) acc[a][r][j] = 0.f;
    int tx = threadIdx.x & 7, ty = threadIdx.x >> 3;
    const float* h1b = g_h1 + (size_t)b*NC*CH1SZ + (size_t)r0*W1S + c0;

    // preload chunk 0
    {
        for (int i = threadIdx.x; i < 3*1156; i += 128) {
            int c = i / 1156; int r2 = i - c*1156;
            int rr = r2 / 34, cc = r2 - rr*34;
            cp_async4(&s_in[0][c][rr*37 + cc], h1b + (size_t)c*CH1SZ + (size_t)rr*W1S + cc);
        }
        cp_commit();
    }
    for (int k = 0; k < C2NCH; k++) {
        cp_wait0();
        __syncthreads();
        if (k + 1 < C2NCH) {
            const float* src = h1b + (size_t)(k+1)*3*CH1SZ;
            float (*dst)[34*37] = s_in[(k+1) & 1];
            for (int i = threadIdx.x; i < 3*1156; i += 128) {
                int c = i / 1156; int r2 = i - c*1156;
                int rr = r2 / 34, cc = r2 - rr*34;
                cp_async4(&dst[c][rr*37 + cc], src + (size_t)c*CH1SZ + (size_t)rr*W1S + cc);
            }
            cp_commit();
        }
        const float (*buf)[34*37] = s_in[k & 1];
#pragma unroll
        for (int c = 0; c < 3; c++) {
            int cg = k*3 + c;
#pragma unroll
            for (int kh = 0; kh < 3; kh++) {
                float a6[6], b6[6];
#pragma unroll
                for (int q = 0; q < 6; q++) {
                    a6[q] = buf[c][(ty + kh)*37 + 4*tx + q];
                    b6[q] = buf[c][(ty + 16 + kh)*37 + 4*tx + q];
                }
#pragma unroll
                for (int oc = 0; oc < 8; oc++) {
                    int wb = oc*432 + cg*9 + kh*3;
                    float w0 = s_w[wb], w1v = s_w[wb+1], w2v = s_w[wb+2];
#pragma unroll
                    for (int jj = 0; jj < 4; jj++) {
                        acc[oc][0][jj] += w0*a6[jj] + w1v*a6[jj+1] + w2v*a6[jj+2];
                        acc[oc][1][jj] += w0*b6[jj] + w1v*b6[jj+1] + w2v*b6[jj+2];
                    }
                }
            }
        }
    }
    // epilogue: tanh, store, fused per-oc stats
    int lane = threadIdx.x & 31, wrp = threadIdx.x >> 5;
    float osum[8], osq[8];
#pragma unroll
    for (int oc = 0; oc < 8; oc++) {
        size_t base = ((size_t)(b*NC + oc0 + oc))*HW;
        float s = 0.f, sq = 0.f;
#pragma unroll
        for (int rsel = 0; rsel < 2; rsel++) {
            int orow = r0 + ty + rsel*16;
#pragma unroll
            for (int jj = 0; jj < 4; jj++) {
                float tv = tanhf(acc[oc][rsel][jj]);
                g_h2[base + (size_t)orow*256 + (c0 + 4*tx + jj)] = tv;
                s += tv; sq += tv*tv;
            }
        }
        osum[oc] = s; osq[oc] = sq;
    }
#pragma unroll
    for (int oc = 0; oc < 8; oc++) {
#pragma unroll
        for (int o = 16; o > 0; o >>= 1) {
            osum[oc] += __shfl_down_sync(0xffffffffu, osum[oc], o);
            osq[oc]  += __shfl_down_sync(0xffffffffu, osq[oc], o);
        }
        if (lane == 0) { s_red[oc][wrp][0] = osum[oc]; s_red[oc][wrp][1] = osq[oc]; }
    }
    __syncthreads();
    if (threadIdx.x < 16) {
        int oc = threadIdx.x >> 1, sel = threadIdx.x & 1;
        float v = s_red[oc][0][sel] + s_red[oc][1][sel] + s_red[oc][2][sel] + s_red[oc][3][sel];
        if (sel) atomicAdd(&g_SS48[0][oc0 + oc], (double)v);
        else     atomicAdd(&g_S48[0][oc0 + oc], (double)v);
    }
}

// ---------------- CHANGE: bn+tanh(h2) -> k2 s2 conv -> sigmoid ----------------
__global__ void k_change(const float* __restrict__ w2) {
    __shared__ float ssc[48], ssh[48], sw[192];
    int t = threadIdx.x;
    if (t < 48)  { ssc[t] = g_scale[1][t]; ssh[t] = g_shift[1][t]; }
    if (t < 192) sw[t] = w2[t];
    __syncthreads();
    int idx = blockIdx.x*256 + t;   // 512*256 = 131072 exactly
    int b = idx >> 14; int q = idx & 16383;
    int i = q >> 7, j = q & 127;
    const float* h2b = g_h2 + ((size_t)b*NC)*HW + (size_t)(2*i)*256 + 2*j;
    float acc = 0.f;
#pragma unroll 4
    for (int c = 0; c < 48; c++) {
        const float* p = h2b + (size_t)c*HW;
        float sc = ssc[c], sh = ssh[c];
        acc += sw[c*4+0]*tanhf(sc*p[0]   + sh);
        acc += sw[c*4+1]*tanhf(sc*p[1]   + sh);
        acc += sw[c*4+2]*tanhf(sc*p[256] + sh);
        acc += sw[c*4+3]*tanhf(sc*p[257] + sh);
    }
    g_chg[idx] = 1.f/(1.f + expf(-acc));
}

// ---------------- cm1: grouped k2 s2 conv (D->NC, g3) ----------------
__global__ void k_cm1(const float* __restrict__ x, const float* __restrict__ w) {
    int idx = blockIdx.x*blockDim.x + threadIdx.x;
    if (idx >= BATCH*NC*HWo) return;
    int q = idx & 16383; int co = idx >> 14;
    int o = co % 48; int b = co / 48;
    int i = q >> 7, j = q & 127;
    int ic0 = (o >> 4)*2;
    const float* xb = x + ((size_t)(b*6 + ic0))*HW + (size_t)(2*i)*256 + 2*j;
    const float* wp = w + o*8;
    float acc = xb[0]*wp[0] + xb[1]*wp[1] + xb[256]*wp[2] + xb[257]*wp[3]
              + xb[HW]*wp[4] + xb[HW+1]*wp[5] + xb[HW+256]*wp[6] + xb[HW+257]*wp[7];
    g_cm1[idx] = acc;
}

// ---------------- conv cm_ct: bn+tanh(cm1) -> k3 pad2 grouped conv -> tanh, 130x130 ----------------
__global__ void __launch_bounds__(128) k_convcm(const float* __restrict__ wct) {
    __shared__ float s_in[8][34*37];
    __shared__ float s_w[576];
    int b = blockIdx.z / 12, ocg = blockIdx.z % 12, oc0 = ocg*4;
    int icb = (oc0 >> 4)*16;
    int r0 = blockIdx.y*32, c0 = blockIdx.x*32;
    for (int i = threadIdx.x; i < 576; i += 128) s_w[i] = wct[oc0*144 + i];
    float acc[4][2][4];
#pragma unroll
    for (int a = 0; a < 4; a++)
#pragma unroll
        for (int r = 0; r < 2; r++)
#pragma unroll
            for (int j = 0; j < 4; j++) acc[a][r][j] = 0.f;
    int tx = threadIdx.x & 7, ty = threadIdx.x >> 3;
    for (int ch0 = 0; ch0 < 16; ch0 += 8) {
        __syncthreads();
        for (int i = threadIdx.x; i < 8*1156; i += 128) {
            int c = i / 1156; int r2 = i - c*1156;
            int rr = r2 / 34, cc = r2 - rr*34;
            int hi = r0 - 2 + rr, wi = c0 - 2 + cc;
            float v = 0.f;
            int cg = icb + ch0 + c;
            if ((unsigned)hi < 128u && (unsigned)wi < 128u) {
                float raw = g_cm1[((size_t)(b*NC + cg))*HWo + hi*128 + wi];
                v = tanhf(g_scale[2][cg]*raw + g_shift[2][cg]);
            }
            s_in[c][rr*37 + cc] = v;
        }
        __syncthreads();
#pragma unroll
        for (int c = 0; c < 8; c++) {
#pragma unroll
            for (int kh = 0; kh < 3; kh++) {
                float a6[6], b6[6];
#pragma unroll
                for (int q = 0; q < 6; q++) {
                    a6[q] = s_in[c][(ty + kh)*37 + 4*tx + q];
                    b6[q] = s_in[c][(ty + 16 + kh)*37 + 4*tx + q];
                }
#pragma unroll
                for (int oc = 0; oc < 4; oc++) {
                    int wb = (oc*16 + ch0 + c)*9 + kh*3;
                    float w0 = s_w[wb], w1v = s_w[wb+1], w2v = s_w[wb+2];
#pragma unroll
                    for (int jj = 0; jj < 4; jj++) {
                        acc[oc][0][jj] += w0*a6[jj] + w1v*a6[jj+1] + w2v*a6[jj+2];
                        acc[oc][1][jj] += w0*b6[jj] + w1v*b6[jj+1] + w2v*b6[jj+2];
                    }
                }
            }
        }
    }
#pragma unroll
    for (int oc = 0; oc < 4; oc++) {
        size_t base = ((size_t)(b*NC + oc0 + oc))*CH3SZ;
#pragma unroll
        for (int rsel = 0; rsel < 2; rsel++) {
            int orow = r0 + ty + rsel*16;
            if (orow >= H3) continue;
#pragma unroll
            for (int jj = 0; jj < 4; jj++) {
                int ocol = c0 + 4*tx + jj;
                if (ocol < H3)
                    g_h3[base + (size_t)orow*W3S + ocol] = tanhf(acc[oc][rsel][jj]);
            }
        }
    }
}

// ---------------- xm: k3 grouped conv (NC->D, g3), out 128x128, tanh ----------------
__global__ void __launch_bounds__(128) k_convxm(const float* __restrict__ wc2) {
    __shared__ float s_in[8][34*37];
    __shared__ float s_w[288];
    int b = blockIdx.z / 3, g = blockIdx.z % 3;
    int r0 = blockIdx.y*32, c0 = blockIdx.x*32;
    for (int i = threadIdx.x; i < 288; i += 128) s_w[i] = wc2[g*288 + i];
    float acc[2][2][4];
#pragma unroll
    for (int a = 0; a < 2; a++)
#pragma unroll
        for (int r = 0; r < 2; r++)
#pragma unroll
            for (int j = 0; j < 4; j++) acc[a][r][j] = 0.f;
    int tx = threadIdx.x & 7, ty = threadIdx.x >> 3;
    for (int ch0 = 0; ch0 < 16; ch0 += 8) {
        __syncthreads();
        for (int i = threadIdx.x; i < 8*1156; i += 128) {
            int c = i / 1156; int r2 = i - c*1156;
            int rr = r2 / 34, cc = r2 - rr*34;
            s_in[c][rr*37 + cc] = g_h3[((size_t)(b*NC + g*16 + ch0 + c))*CH3SZ
                                   + (size_t)(r0 + rr)*W3S + (c0 + cc)];
        }
        __syncthreads();
#pragma unroll
        for (int c = 0; c < 8; c++) {
#pragma unroll
            for (int kh = 0; kh < 3; kh++) {
                float a6[6], b6[6];
#pragma unroll
                for (int q = 0; q < 6; q++) {
                    a6[q] = s_in[c][(ty + kh)*37 + 4*tx + q];
                    b6[q] = s_in[c][(ty + 16 + kh)*37 + 4*tx + q];
                }
#pragma unroll
                for (int oc = 0; oc < 2; oc++) {
                    int wb = (oc*16 + ch0 + c)*9 + kh*3;
                    float w0 = s_w[wb], w1v = s_w[wb+1], w2v = s_w[wb+2];
#pragma unroll
                    for (int jj = 0; jj < 4; jj++) {
                        acc[oc][0][jj] += w0*a6[jj] + w1v*a6[jj+1] + w2v*a6[jj+2];
                        acc[oc][1][jj] += w0*b6[jj] + w1v*b6[jj+1] + w2v*b6[jj+2];
                    }
                }
            }
        }
    }
#pragma unroll
    for (int oc = 0; oc < 2; oc++) {
        size_t base = ((size_t)(b*6 + g*2 + oc))*HWo;
#pragma unroll
        for (int rsel = 0; rsel < 2; rsel++) {
            int orow = r0 + ty + rsel*16;
#pragma unroll
            for (int jj = 0; jj < 4; jj++)
                g_xm[base + (size_t)orow*128 + (c0 + 4*tx + jj)] = tanhf(acc[oc][rsel][jj]);
        }
    }
}

// ---------------- final: born (fused 1x1/BN/tanh/1x1) + blend + partial sigmoid ----------------
__global__ void k_final(const float* __restrict__ w1, const float* __restrict__ w2,
                        float* __restrict__ out) {
    __shared__ float sw1[288], sw2[288], ssc[48], ssh[48];
    int t = threadIdx.x;
    for (int i = t; i < 288; i += 256) { sw1[i] = w1[i]; sw2[i] = w2[i]; }
    if (t < 48)  { ssc[t] = g_scale[3][t]; ssh[t] = g_shift[3][t]; }
    __syncthreads();
    int idx = blockIdx.x*256 + t;    // 512*256 = 131072 exactly
    int b = idx >> 14; int q = idx & 16383;
    const float* xb = g_xm + (size_t)b*6*HWo + q;
    float v[6];
#pragma unroll
    for (int d = 0; d < 6; d++) v[d] = xb[(size_t)d*HWo];
    float bo[6] = {0.f,0.f,0.f,0.f,0.f,0.f};
#pragma unroll 8
    for (int c = 0; c < 48; c++) {
        const float* w = sw1 + c*6;
        float u = w[0]*v[0] + w[1]*v[1] + w[2]*v[2] + w[3]*v[3] + w[4]*v[4] + w[5]*v[5];
        float tv = tanhf(ssc[c]*u + ssh[c]);
#pragma unroll
        for (int d = 0; d < 6; d++) bo[d] += sw2[d*48 + c]*tv;
    }
    float ch = g_chg[idx];
#pragma unroll
    for (int d = 0; d < 6; d++) {
        float r = v[d]*(1.f - ch) + ch*bo[d];
        if (d < 3) r = 1.f/(1.f + expf(-r));
        out[((size_t)(b*6 + d))*HWo + q] = r;
    }
}

// ---------------- launch ----------------
extern "C" void kernel_launch(void* const* d_in, const int* in_sizes, int n_in,
                              void* d_out, int out_size) {
    (void)in_sizes; (void)n_in; (void)out_size;
    const float* x     = (const float*)d_in[0];
    const float* ce_w1 = (const float*)d_in[1];
    const float* ce_g  = (const float*)d_in[2];
    const float* ce_b  = (const float*)d_in[3];
    const float* ce_w2 = (const float*)d_in[4];
    const float* md_ct = (const float*)d_in[5];
    const float* md_c1 = (const float*)d_in[6];
    const float* md_g  = (const float*)d_in[7];
    const float* md_b  = (const float*)d_in[8];
    const float* md_c2 = (const float*)d_in[9];
    const float* cm_w1 = (const float*)d_in[10];
    const float* cm_g  = (const float*)d_in[11];
    const float* cm_b  = (const float*)d_in[12];
    const float* cm_ct = (const float*)d_in[13];
    const float* cm_c2 = (const float*)d_in[14];
    const float* bo_w1 = (const float*)d_in[15];
    const float* bo_g  = (const float*)d_in[16];
    const float* bo_b  = (const float*)d_in[17];
    const float* bo_w2 = (const float*)d_in[18];
    float* out = (float*)d_out;

    k_zero<<<1, 128>>>();

    // compenv branch (shift-invariance collapse)
    k_stats6<<<512, 256>>>(x, 0);
    k_final6<<<1, 64>>>(ce_w1, ce_g, ce_b, 0, 0);
    k_E<<<2048, 256>>>(x, ce_w1, ce_w2);

    // merge determinant branch
    k_conv1<<<dim3(9, 9, 48), 128>>>(x, md_ct);
    k_conv2<<<dim3(8, 8, 48), 128>>>(md_c1);           // fused md stats
    k_final48<<<1, 64>>>(md_g, md_b, 0, 1, 524288.0);
    k_change<<<512, 256>>>(md_c2);

    // cell merge branch
    k_cm1<<<(BATCH*NC*HWo + 255)/256, 256>>>(x, cm_w1);
    k_stats48<<<dim3(48, 32), 256>>>(1);
    k_final48<<<1, 64>>>(cm_g, cm_b, 1, 2, 131072.0);
    k_convcm<<<dim3(5, 5, 96), 128>>>(cm_ct);
    k_convxm<<<dim3(4, 4, 24), 128>>>(cm_c2);

    // born + blend
    k_stats6<<<512, 256>>>(x, 1);
    k_final6<<<1, 64>>>(bo_w1, bo_g, bo_b, 1, 3);
    k_final<<<512, 256>>>(bo_w1, bo_w2, out);
}

// round 10
// speedup vs baseline: 1.4727x; 1.1674x over previous
#include <cuda_runtime.h>
#include <math.h>
#include <stdint.h>

#define BATCH 8
#define DCH 6
#define NC 48
#define HW 65536            // 256*256
#define H1 258
#define W1S 264
#define CH1SZ (H1*W1S)      // 68112
#define H3 130
#define W3S 132
#define CH3SZ (H3*W3S)      // 17160
#define HWo 16384           // 128*128
#define SS 36               // smem tile stride (floats), 16B-aligned rows

// ---------------- scratch (static device memory; no allocations) ----------------
__device__ float g_E[BATCH*HW];                          // 2 MB
__device__ float g_h1[(size_t)BATCH*NC*CH1SZ];           // ~105 MB  tanh(conv1)
__device__ float g_h2[(size_t)BATCH*NC*HW];              // ~101 MB  tanh(conv2)
__device__ float g_cm1[(size_t)BATCH*NC*HWo];            // 25 MB    raw cm conv
__device__ float g_h3[(size_t)BATCH*NC*CH3SZ];           // 26 MB    tanh(conv cm_ct)
__device__ float g_xm[BATCH*DCH*HWo];                    // 3 MB
__device__ float g_chg[BATCH*HWo];                       // 0.5 MB

__device__ double g_S6[2][6];     // 0: x moments, 1: xm moments
__device__ double g_M6[2][21];
__device__ double g_S48[2][48];   // 0: h2, 1: cm1
__device__ double g_SS48[2][48];
__device__ float  g_scale[4][48]; // 0=ce,1=md,2=cm,3=bo
__device__ float  g_shift[4][48];

__device__ const int g_DX[8] = {0,1,1,1,0,-1,-1,-1};
__device__ const int g_DY[8] = {1,1,0,-1,-1,-1,0,1};

__device__ __forceinline__ void cp_async16(void* sdst, const void* gsrc) {
    unsigned s = (unsigned)__cvta_generic_to_shared(sdst);
    asm volatile("cp.async.ca.shared.global [%0], [%1], 16;\n" :: "r"(s), "l"(gsrc));
}
__device__ __forceinline__ void cp_async8(void* sdst, const void* gsrc) {
    unsigned s = (unsigned)__cvta_generic_to_shared(sdst);
    asm volatile("cp.async.ca.shared.global [%0], [%1], 8;\n" :: "r"(s), "l"(gsrc));
}
__device__ __forceinline__ void cp_commit() {
    asm volatile("cp.async.commit_group;\n");
}
__device__ __forceinline__ void cp_wait0() {
    asm volatile("cp.async.wait_group 0;\n");
}
// HW tanh (sm_75+). Used ONLY in the md/CHANGE branch (sigmoid-squashed).
__device__ __forceinline__ float tanha(float x) {
    float y; asm("tanh.approx.f32 %0, %1;" : "=f"(y) : "f"(x)); return y;
}

// ---------------- zero stats ----------------
__global__ void k_zero() {
    int t = threadIdx.x;
    if (t < 12) (&g_S6[0][0])[t] = 0.0;
    if (t < 42) (&g_M6[0][0])[t] = 0.0;
    if (t < 96) (&g_S48[0][0])[t] = 0.0;
    if (t < 96) (&g_SS48[0][0])[t] = 0.0;
}

// ---------------- 6-channel first/second moments (x or xm) ----------------
__global__ void k_stats6(const float* __restrict__ xin, int which) {
    const float* p = which ? (const float*)g_xm : xin;
    int HWl = which ? HWo : HW;
    double* S = g_S6[which];
    double* M = g_M6[which];
    int total = BATCH*HWl;
    double mu[6]; double mm[21];
#pragma unroll
    for (int d = 0; d < 6; d++) mu[d] = 0.0;
#pragma unroll
    for (int i = 0; i < 21; i++) mm[i] = 0.0;
    for (int idx = blockIdx.x*blockDim.x + threadIdx.x; idx < total;
         idx += gridDim.x*blockDim.x) {
        int b = idx / HWl; int q = idx - b*HWl;
        const float* base = p + (size_t)b*6*HWl + q;
        float v[6];
#pragma unroll
        for (int d = 0; d < 6; d++) v[d] = base[(size_t)d*HWl];
        int t = 0;
#pragma unroll
        for (int d = 0; d < 6; d++) {
            mu[d] += (double)v[d];
#pragma unroll
            for (int e = d; e < 6; e++) { mm[t] += (double)v[d]*(double)v[e]; t++; }
        }
    }
#pragma unroll
    for (int o = 16; o > 0; o >>= 1) {
#pragma unroll
        for (int d = 0; d < 6; d++)  mu[d] += __shfl_down_sync(0xffffffffu, mu[d], o);
#pragma unroll
        for (int i = 0; i < 21; i++) mm[i] += __shfl_down_sync(0xffffffffu, mm[i], o);
    }
    __shared__ double sS[6], sM[21];
    if (threadIdx.x < 6)  sS[threadIdx.x] = 0.0;
    if (threadIdx.x < 21) sM[threadIdx.x] = 0.0;
    __syncthreads();
    if ((threadIdx.x & 31) == 0) {
        for (int d = 0; d < 6; d++)  atomicAdd(&sS[d], mu[d]);
        for (int i = 0; i < 21; i++) atomicAdd(&sM[i], mm[i]);
    }
    __syncthreads();
    if (threadIdx.x < 6)  atomicAdd(&S[threadIdx.x], sS[threadIdx.x]);
    if (threadIdx.x < 21) atomicAdd(&M[threadIdx.x], sM[threadIdx.x]);
}

// ---------------- analytic BN for 1x1 convs (ce / bo) ----------------
__global__ void k_final6(const float* __restrict__ w1, const float* __restrict__ gg,
                         const float* __restrict__ bb, int which, int outi) {
    int c = threadIdx.x; if (c >= 48) return;
    double N = which ? (double)(BATCH*HWo) : (double)(BATCH*HW);
    const double* S = g_S6[which];
    const double* M = g_M6[which];
    double wl[6]; double m = 0.0;
    for (int d = 0; d < 6; d++) { wl[d] = (double)w1[c*6+d]; m += wl[d]*(S[d]/N); }
    double e2 = 0.0; int t = 0;
    for (int d = 0; d < 6; d++)
        for (int e = d; e < 6; e++) {
            double coef = (d == e) ? 1.0 : 2.0;
            e2 += coef*wl[d]*wl[e]*(M[t]/N); t++;
        }
    double var = e2 - m*m;
    if (var < 0.0) var = 0.0;
    double sc = (double)gg[c] / sqrt(var + 1e-5);
    g_scale[outi][c] = (float)sc;
    g_shift[outi][c] = (float)((double)bb[c] - sc*m);
}

// ---------------- per-channel sum/sumsq over 48-ch tensors (cm1) ----------------
__global__ void k_stats48(int which) {
    const float* p = which ? (const float*)g_cm1 : (const float*)g_h2;
    int HWl = which ? HWo : HW;
    int c = blockIdx.x;
    int total = BATCH*HWl;
    double s = 0.0, ss = 0.0;
    for (int idx = blockIdx.y*blockDim.x + threadIdx.x; idx < total;
         idx += gridDim.y*blockDim.x) {
        int b = idx / HWl; int q = idx - b*HWl;
        float v = p[((size_t)(b*NC + c))*HWl + q];
        s += (double)v; ss += (double)v*(double)v;
    }
#pragma unroll
    for (int o = 16; o > 0; o >>= 1) {
        s  += __shfl_down_sync(0xffffffffu, s, o);
        ss += __shfl_down_sync(0xffffffffu, ss, o);
    }
    __shared__ double sh[2];
    if (threadIdx.x == 0) { sh[0] = 0.0; sh[1] = 0.0; }
    __syncthreads();
    if ((threadIdx.x & 31) == 0) { atomicAdd(&sh[0], s); atomicAdd(&sh[1], ss); }
    __syncthreads();
    if (threadIdx.x == 0) {
        atomicAdd(&g_S48[which][c], sh[0]);
        atomicAdd(&g_SS48[which][c], sh[1]);
    }
}

__global__ void k_final48(const float* __restrict__ gg, const float* __restrict__ bb,
                          int which, int outi, double N) {
    int c = threadIdx.x; if (c >= 48) return;
    double mean = g_S48[which][c]/N;
    double var  = g_SS48[which][c]/N - mean*mean;
    if (var < 0.0) var = 0.0;
    double sc = (double)gg[c] / sqrt(var + 1e-5);
    g_scale[outi][c] = (float)sc;
    g_shift[outi][c] = (float)((double)bb[c] - sc*mean);
}

// ---------------- E map: fused 1x1 conv + analytic BN + tanh + 1x1 conv ----------------
__global__ void k_E(const float* __restrict__ x, const float* __restrict__ w1,
                    const float* __restrict__ w2) {
    __shared__ float sw1[288], sw2[48], ssc[48], ssh[48];
    int t = threadIdx.x;
    for (int i = t; i < 288; i += 256) sw1[i] = w1[i];
    if (t < 48) { sw2[t] = w2[t]; ssc[t] = g_scale[0][t]; ssh[t] = g_shift[0][t]; }
    __syncthreads();
    int idx = blockIdx.x*blockDim.x + t;   // 2048*256 = 524288 exactly
    int b = idx >> 16; int q = idx & 65535;
    const float* base = x + (size_t)b*6*HW + q;
    float v0 = base[0], v1 = base[HW], v2 = base[2*HW];
    float v3 = base[3*HW], v4 = base[4*HW], v5 = base[5*HW];
    float sum = 0.f;
#pragma unroll 8
    for (int c = 0; c < 48; c++) {
        const float* w = sw1 + c*6;
        float u = w[0]*v0 + w[1]*v1 + w[2]*v2 + w[3]*v3 + w[4]*v4 + w[5]*v5;
        sum += sw2[c]*tanha(ssc[c]*u + ssh[c]);
    }
    g_E[idx] = sum;
}

// ---------------- conv1: te(10ch, virtual) -> 48, k3, pad2, out 258x258, tanh ----------------
__global__ void __launch_bounds__(128) k_conv1(const float* __restrict__ x,
                                               const float* __restrict__ wct) {
    __shared__ float s_in[5][34*SS];
    __shared__ float4 s_w4[240];          // [oc8][cg10][kh3]
    int b = blockIdx.z / 6, ocg = blockIdx.z % 6, oc0 = ocg*8;
    int r0 = blockIdx.y*32, c0 = blockIdx.x*32;
    for (int i = threadIdx.x; i < 240; i += 128) {
        int oc = i/30, rem = i - oc*30, cg = rem/3, kh = rem - cg*3;
        const float* ws = wct + (size_t)(oc0 + oc)*90 + cg*9 + kh*3;
        s_w4[i] = make_float4(ws[0], ws[1], ws[2], 0.f);
    }
    float acc[8][2][4];
#pragma unroll
    for (int a = 0; a < 8; a++)
#pragma unroll
        for (int r = 0; r < 2; r++)
#pragma unroll
            for (int j = 0; j < 4; j++) acc[a][r][j] = 0.f;
    int tx = threadIdx.x & 7, ty = threadIdx.x >> 3;   // tx 0..7, ty 0..15
    const float* Eb = g_E + (size_t)b*HW;
    for (int ch0 = 0; ch0 < 10; ch0 += 5) {
        __syncthreads();
        for (int i = threadIdx.x; i < 5*1156; i += 128) {
            int c = i / 1156; int r2 = i - c*1156;
            int rr = r2 / 34, cc = r2 - rr*34;
            int hi = r0 - 2 + rr, wi = c0 - 2 + cc;
            float v = 0.f;
            int cg = ch0 + c;
            if ((unsigned)hi < 256u && (unsigned)wi < 256u) {
                if (cg < 2) v = x[((size_t)(b*6 + cg))*HW + hi*256 + wi];
                else {
                    int k = cg - 2;
                    int hh = (hi + g_DY[k]) & 255;
                    int wz = (wi - g_DX[k]) & 255;
                    v = Eb[hh*256 + wz];
                }
            }
            s_in[c][rr*SS + cc] = v;
        }
        __syncthreads();
#pragma unroll
        for (int c = 0; c < 5; c++) {
            int cg = ch0 + c;
#pragma unroll
            for (int kh = 0; kh < 3; kh++) {
                const float* pa = &s_in[c][(ty + kh)*SS + 4*tx];
                const float* pb = &s_in[c][(ty + 16 + kh)*SS + 4*tx];
                float4 av = *(const float4*)pa; float2 av2 = *(const float2*)(pa + 4);
                float4 bv = *(const float4*)pb; float2 bv2 = *(const float2*)(pb + 4);
                float a6[6] = {av.x, av.y, av.z, av.w, av2.x, av2.y};
                float b6[6] = {bv.x, bv.y, bv.z, bv.w, bv2.x, bv2.y};
#pragma unroll
                for (int oc = 0; oc < 8; oc++) {
                    float4 wv = s_w4[(oc*10 + cg)*3 + kh];
#pragma unroll
                    for (int jj = 0; jj < 4; jj++) {
                        acc[oc][0][jj] += wv.x*a6[jj] + wv.y*a6[jj+1] + wv.z*a6[jj+2];
                        acc[oc][1][jj] += wv.x*b6[jj] + wv.y*b6[jj+1] + wv.z*b6[jj+2];
                    }
                }
            }
        }
    }
#pragma unroll
    for (int oc = 0; oc < 8; oc++) {
        size_t base = ((size_t)(b*NC + oc0 + oc))*CH1SZ;
#pragma unroll
        for (int rsel = 0; rsel < 2; rsel++) {
            int orow = r0 + ty + rsel*16;
            if (orow >= H1) continue;
#pragma unroll
            for (int jj = 0; jj < 4; jj++) {
                int ocol = c0 + 4*tx + jj;
                if (ocol < H1)
                    g_h1[base + (size_t)orow*W1S + ocol] = tanha(acc[oc][rsel][jj]);
            }
        }
    }
}

// ---------------- conv2: 48 -> 48, k3, 256x256 out, tanh (dominant kernel) ----------------
// 8 oc/block, 16B cp.async double-buffered (16 chunks x 3 ic), float4 weights,
// fused per-channel sum/sumsq stats (md BN).
#define C2NCH 16
__global__ void __launch_bounds__(128) k_conv2(const float* __restrict__ wc1) {
    __shared__ float s_in[2][3][34*SS];   // 29376 B
    __shared__ float4 s_w4[8*48*3];       // 18432 B  [oc][ic][kh]
    __shared__ float s_red[8][4][2];
    int b = blockIdx.z / 6, ocg = blockIdx.z % 6, oc0 = ocg*8;
    int r0 = blockIdx.y*32, c0 = blockIdx.x*32;
    for (int i = threadIdx.x; i < 8*48*3; i += 128) {
        int oc = i/144, rem = i - oc*144, ic = rem/3, kh = rem - ic*3;
        const float* ws = wc1 + (size_t)(oc0 + oc)*432 + ic*9 + kh*3;
        s_w4[i] = make_float4(ws[0], ws[1], ws[2], 0.f);
    }
    float acc[8][2][4];
#pragma unroll
    for (int a = 0; a < 8; a++)
#pragma unroll
        for (int r = 0; r < 2; r++)
#pragma unroll
            for (int j = 0; j < 4; j++) acc[a][r][j] = 0.f;
    int tx = threadIdx.x & 7, ty = threadIdx.x >> 3;
    const float* h1b = g_h1 + (size_t)b*NC*CH1SZ + (size_t)r0*W1S + c0;

    // vectorized tile fill: 3 ch x 34 rows x (8 x 16B + 1 x 8B) = 918 ops
    // i -> c = i/306, row = (i%306)/9, seg = i%9
    {
        for (int i = threadIdx.x; i < 918; i += 128) {
            int c = i/306, rem = i - c*306, row = rem/9, seg = rem - row*9;
            const float* src = h1b + (size_t)c*CH1SZ + (size_t)row*W1S + seg*4;
            float* dst = &s_in[0][c][row*SS + seg*4];
            if (seg < 8) cp_async16(dst, src); else cp_async8(dst, src);
        }
        cp_commit();
    }
    for (int k = 0; k < C2NCH; k++) {
        cp_wait0();
        __syncthreads();
        if (k + 1 < C2NCH) {
            const float* src0 = h1b + (size_t)(k+1)*3*CH1SZ;
            float (*dst0)[34*SS] = s_in[(k+1) & 1];
            for (int i = threadIdx.x; i < 918; i += 128) {
                int c = i/306, rem = i - c*306, row = rem/9, seg = rem - row*9;
                const float* src = src0 + (size_t)c*CH1SZ + (size_t)row*W1S + seg*4;
                float* dst = &dst0[c][row*SS + seg*4];
                if (seg < 8) cp_async16(dst, src); else cp_async8(dst, src);
            }
            cp_commit();
        }
        const float (*buf)[34*SS] = s_in[k & 1];
#pragma unroll
        for (int c = 0; c < 3; c++) {
            int cg = k*3 + c;
#pragma unroll
            for (int kh = 0; kh < 3; kh++) {
                const float* pa = &buf[c][(ty + kh)*SS + 4*tx];
                const float* pb = &buf[c][(ty + 16 + kh)*SS + 4*tx];
                float4 av = *(const float4*)pa; float2 av2 = *(const float2*)(pa + 4);
                float4 bv = *(const float4*)pb; float2 bv2 = *(const float2*)(pb + 4);
                float a6[6] = {av.x, av.y, av.z, av.w, av2.x, av2.y};
                float b6[6] = {bv.x, bv.y, bv.z, bv.w, bv2.x, bv2.y};
#pragma unroll
                for (int oc = 0; oc < 8; oc++) {
                    float4 wv = s_w4[(oc*48 + cg)*3 + kh];
#pragma unroll
                    for (int jj = 0; jj < 4; jj++) {
                        acc[oc][0][jj] += wv.x*a6[jj] + wv.y*a6[jj+1] + wv.z*a6[jj+2];
                        acc[oc][1][jj] += wv.x*b6[jj] + wv.y*b6[jj+1] + wv.z*b6[jj+2];
                    }
                }
            }
        }
    }
    // epilogue: tanh, store, fused per-oc stats
    int lane = threadIdx.x & 31, wrp = threadIdx.x >> 5;
    float osum[8], osq[8];
#pragma unroll
    for (int oc = 0; oc < 8; oc++) {
        size_t base = ((size_t)(b*NC + oc0 + oc))*HW;
        float s = 0.f, sq = 0.f;
#pragma unroll
        for (int rsel = 0; rsel < 2; rsel++) {
            int orow = r0 + ty + rsel*16;
#pragma unroll
            for (int jj = 0; jj < 4; jj++) {
                float tv = tanha(acc[oc][rsel][jj]);
                g_h2[base + (size_t)orow*256 + (c0 + 4*tx + jj)] = tv;
                s += tv; sq += tv*tv;
            }
        }
        osum[oc] = s; osq[oc] = sq;
    }
#pragma unroll
    for (int oc = 0; oc < 8; oc++) {
#pragma unroll
        for (int o = 16; o > 0; o >>= 1) {
            osum[oc] += __shfl_down_sync(0xffffffffu, osum[oc], o);
            osq[oc]  += __shfl_down_sync(0xffffffffu, osq[oc], o);
        }
        if (lane == 0) { s_red[oc][wrp][0] = osum[oc]; s_red[oc][wrp][1] = osq[oc]; }
    }
    __syncthreads();
    if (threadIdx.x < 16) {
        int oc = threadIdx.x >> 1, sel = threadIdx.x & 1;
        float v = s_red[oc][0][sel] + s_red[oc][1][sel] + s_red[oc][2][sel] + s_red[oc][3][sel];
        if (sel) atomicAdd(&g_SS48[0][oc0 + oc], (double)v);
        else     atomicAdd(&g_S48[0][oc0 + oc], (double)v);
    }
}

// ---------------- CHANGE: bn+tanh(h2) -> k2 s2 conv -> sigmoid ----------------
__global__ void k_change(const float* __restrict__ w2) {
    __shared__ float ssc[48], ssh[48], sw[192];
    int t = threadIdx.x;
    if (t < 48)  { ssc[t] = g_scale[1][t]; ssh[t] = g_shift[1][t]; }
    if (t < 192) sw[t] = w2[t];
    __syncthreads();
    int idx = blockIdx.x*256 + t;   // 512*256 = 131072 exactly
    int b = idx >> 14; int q = idx & 16383;
    int i = q >> 7, j = q & 127;
    const float* h2b = g_h2 + ((size_t)b*NC)*HW + (size_t)(2*i)*256 + 2*j;
    float acc = 0.f;
#pragma unroll 4
    for (int c = 0; c < 48; c++) {
        const float* p = h2b + (size_t)c*HW;
        float sc = ssc[c], sh = ssh[c];
        acc += sw[c*4+0]*tanha(sc*p[0]   + sh);
        acc += sw[c*4+1]*tanha(sc*p[1]   + sh);
        acc += sw[c*4+2]*tanha(sc*p[256] + sh);
        acc += sw[c*4+3]*tanha(sc*p[257] + sh);
    }
    g_chg[idx] = 1.f/(1.f + expf(-acc));
}

// ---------------- cm1: grouped k2 s2 conv (D->NC, g3) ----------------
__global__ void k_cm1(const float* __restrict__ x, const float* __restrict__ w) {
    int idx = blockIdx.x*blockDim.x + threadIdx.x;
    if (idx >= BATCH*NC*HWo) return;
    int q = idx & 16383; int co = idx >> 14;
    int o = co % 48; int b = co / 48;
    int i = q >> 7, j = q & 127;
    int ic0 = (o >> 4)*2;
    const float* xb = x + ((size_t)(b*6 + ic0))*HW + (size_t)(2*i)*256 + 2*j;
    const float* wp = w + o*8;
    float acc = xb[0]*wp[0] + xb[1]*wp[1] + xb[256]*wp[2] + xb[257]*wp[3]
              + xb[HW]*wp[4] + xb[HW+1]*wp[5] + xb[HW+256]*wp[6] + xb[HW+257]*wp[7];
    g_cm1[idx] = acc;
}

// ---------------- conv cm_ct: bn+tanh(cm1) -> k3 pad2 grouped conv -> tanh, 130x130 ----------------
__global__ void __launch_bounds__(128) k_convcm(const float* __restrict__ wct) {
    __shared__ float s_in[8][34*SS];
    __shared__ float4 s_w4[192];          // [oc4][ic16][kh3]
    int b = blockIdx.z / 12, ocg = blockIdx.z % 12, oc0 = ocg*4;
    int icb = (oc0 >> 4)*16;
    int r0 = blockIdx.y*32, c0 = blockIdx.x*32;
    for (int i = threadIdx.x; i < 192; i += 128) {
        int oc = i/48, rem = i - oc*48, ic = rem/3, kh = rem - ic*3;
        const float* ws = wct + (size_t)(oc0 + oc)*144 + ic*9 + kh*3;
        s_w4[i] = make_float4(ws[0], ws[1], ws[2], 0.f);
    }
    float acc[4][2][4];
#pragma unroll
    for (int a = 0; a < 4; a++)
#pragma unroll
        for (int r = 0; r < 2; r++)
#pragma unroll
            for (int j = 0; j < 4; j++) acc[a][r][j] = 0.f;
    int tx = threadIdx.x & 7, ty = threadIdx.x >> 3;
    for (int ch0 = 0; ch0 < 16; ch0 += 8) {
        __syncthreads();
        for (int i = threadIdx.x; i < 8*1156; i += 128) {
            int c = i / 1156; int r2 = i - c*1156;
            int rr = r2 / 34, cc = r2 - rr*34;
            int hi = r0 - 2 + rr, wi = c0 - 2 + cc;
            float v = 0.f;
            int cg = icb + ch0 + c;
            if ((unsigned)hi < 128u && (unsigned)wi < 128u) {
                float raw = g_cm1[((size_t)(b*NC + cg))*HWo + hi*128 + wi];
                v = tanhf(g_scale[2][cg]*raw + g_shift[2][cg]);
            }
            s_in[c][rr*SS + cc] = v;
        }
        __syncthreads();
#pragma unroll
        for (int c = 0; c < 8; c++) {
#pragma unroll
            for (int kh = 0; kh < 3; kh++) {
                const float* pa = &s_in[c][(ty + kh)*SS + 4*tx];
                const float* pb = &s_in[c][(ty + 16 + kh)*SS + 4*tx];
                float4 av = *(const float4*)pa; float2 av2 = *(const float2*)(pa + 4);
                float4 bv = *(const float4*)pb; float2 bv2 = *(const float2*)(pb + 4);
                float a6[6] = {av.x, av.y, av.z, av.w, av2.x, av2.y};
                float b6[6] = {bv.x, bv.y, bv.z, bv.w, bv2.x, bv2.y};
#pragma unroll
                for (int oc = 0; oc < 4; oc++) {
                    float4 wv = s_w4[(oc*16 + ch0 + c)*3 + kh];
#pragma unroll
                    for (int jj = 0; jj < 4; jj++) {
                        acc[oc][0][jj] += wv.x*a6[jj] + wv.y*a6[jj+1] + wv.z*a6[jj+2];
                        acc[oc][1][jj] += wv.x*b6[jj] + wv.y*b6[jj+1] + wv.z*b6[jj+2];
                    }
                }
            }
        }
    }
#pragma unroll
    for (int oc = 0; oc < 4; oc++) {
        size_t base = ((size_t)(b*NC + oc0 + oc))*CH3SZ;
#pragma unroll
        for (int rsel = 0; rsel < 2; rsel++) {
            int orow = r0 + ty + rsel*16;
            if (orow >= H3) continue;
#pragma unroll
            for (int jj = 0; jj < 4; jj++) {
                int ocol = c0 + 4*tx + jj;
                if (ocol < H3)
                    g_h3[base + (size_t)orow*W3S + ocol] = tanhf(acc[oc][rsel][jj]);
            }
        }
    }
}

// ---------------- xm: k3 grouped conv (NC->D, g3), out 128x128, tanh ----------------
__global__ void __launch_bounds__(128) k_convxm(const float* __restrict__ wc2) {
    __shared__ float s_in[8][34*SS];
    __shared__ float4 s_w4[96];           // [oc2][ic16][kh3]
    int b = blockIdx.z / 3, g = blockIdx.z % 3;
    int r0 = blockIdx.y*32, c0 = blockIdx.x*32;
    for (int i = threadIdx.x; i < 96; i += 128) {
        int oc = i/48, rem = i - oc*48, ic = rem/3, kh = rem - ic*3;
        const float* ws = wc2 + (size_t)g*288 + oc*144 + ic*9 + kh*3;
        s_w4[i] = make_float4(ws[0], ws[1], ws[2], 0.f);
    }
    float acc[2][2][4];
#pragma unroll
    for (int a = 0; a < 2; a++)
#pragma unroll
        for (int r = 0; r < 2; r++)
#pragma unroll
            for (int j = 0; j < 4; j++) acc[a][r][j] = 0.f;
    int tx = threadIdx.x & 7, ty = threadIdx.x >> 3;
    for (int ch0 = 0; ch0 < 16; ch0 += 8) {
        __syncthreads();
        for (int i = threadIdx.x; i < 8*1156; i += 128) {
            int c = i / 1156; int r2 = i - c*1156;
            int rr = r2 / 34, cc = r2 - rr*34;
            s_in[c][rr*SS + cc] = g_h3[((size_t)(b*NC + g*16 + ch0 + c))*CH3SZ
                                   + (size_t)(r0 + rr)*W3S + (c0 + cc)];
        }
        __syncthreads();
#pragma unroll
        for (int c = 0; c < 8; c++) {
#pragma unroll
            for (int kh = 0; kh < 3; kh++) {
                const float* pa = &s_in[c][(ty + kh)*SS + 4*tx];
                const float* pb = &s_in[c][(ty + 16 + kh)*SS + 4*tx];
                float4 av = *(const float4*)pa; float2 av2 = *(const float2*)(pa + 4);
                float4 bv = *(const float4*)pb; float2 bv2 = *(const float2*)(pb + 4);
                float a6[6] = {av.x, av.y, av.z, av.w, av2.x, av2.y};
                float b6[6] = {bv.x, bv.y, bv.z, bv.w, bv2.x, bv2.y};
#pragma unroll
                for (int oc = 0; oc < 2; oc++) {
                    float4 wv = s_w4[(oc*16 + ch0 + c)*3 + kh];
#pragma unroll
                    for (int jj = 0; jj < 4; jj++) {
                        acc[oc][0][jj] += wv.x*a6[jj] + wv.y*a6[jj+1] + wv.z*a6[jj+2];
                        acc[oc][1][jj] += wv.x*b6[jj] + wv.y*b6[jj+1] + wv.z*b6[jj+2];
                    }
                }
            }
        }
    }
#pragma unroll
    for (int oc = 0; oc < 2; oc++) {
        size_t base = ((size_t)(b*6 + g*2 + oc))*HWo;
#pragma unroll
        for (int rsel = 0; rsel < 2; rsel++) {
            int orow = r0 + ty + rsel*16;
#pragma unroll
            for (int jj = 0; jj < 4; jj++)
                g_xm[base + (size_t)orow*128 + (c0 + 4*tx + jj)] = tanhf(acc[oc][rsel][jj]);
        }
    }
}

// ---------------- final: born (fused 1x1/BN/tanh/1x1) + blend + partial sigmoid ----------------
__global__ void k_final(const float* __restrict__ w1, const float* __restrict__ w2,
                        float* __restrict__ out) {
    __shared__ float sw1[288], sw2[288], ssc[48], ssh[48];
    int t = threadIdx.x;
    for (int i = t; i < 288; i += 256) { sw1[i] = w1[i]; sw2[i] = w2[i]; }
    if (t < 48)  { ssc[t] = g_scale[3][t]; ssh[t] = g_shift[3][t]; }
    __syncthreads();
    int idx = blockIdx.x*256 + t;    // 512*256 = 131072 exactly
    int b = idx >> 14; int q = idx & 16383;
    const float* xb = g_xm + (size_t)b*6*HWo + q;
    float v[6];
#pragma unroll
    for (int d = 0; d < 6; d++) v[d] = xb[(size_t)d*HWo];
    float bo[6] = {0.f,0.f,0.f,0.f,0.f,0.f};
#pragma unroll 8
    for (int c = 0; c < 48; c++) {
        const float* w = sw1 + c*6;
        float u = w[0]*v[0] + w[1]*v[1] + w[2]*v[2] + w[3]*v[3] + w[4]*v[4] + w[5]*v[5];
        float tv = tanhf(ssc[c]*u + ssh[c]);
#pragma unroll
        for (int d = 0; d < 6; d++) bo[d] += sw2[d*48 + c]*tv;
    }
    float ch = g_chg[idx];
#pragma unroll
    for (int d = 0; d < 6; d++) {
        float r = v[d]*(1.f - ch) + ch*bo[d];
        if (d < 3) r = 1.f/(1.f + expf(-r));
        out[((size_t)(b*6 + d))*HWo + q] = r;
    }
}

// ---------------- launch ----------------
extern "C" void kernel_launch(void* const* d_in, const int* in_sizes, int n_in,
                              void* d_out, int out_size) {
    (void)in_sizes; (void)n_in; (void)out_size;
    const float* x     = (const float*)d_in[0];
    const float* ce_w1 = (const float*)d_in[1];
    const float* ce_g  = (const float*)d_in[2];
    const float* ce_b  = (const float*)d_in[3];
    const float* ce_w2 = (const float*)d_in[4];
    const float* md_ct = (const float*)d_in[5];
    const float* md_c1 = (const float*)d_in[6];
    const float* md_g  = (const float*)d_in[7];
    const float* md_b  = (const float*)d_in[8];
    const float* md_c2 = (const float*)d_in[9];
    const float* cm_w1 = (const float*)d_in[10];
    const float* cm_g  = (const float*)d_in[11];
    const float* cm_b  = (const float*)d_in[12];
    const float* cm_ct = (const float*)d_in[13];
    const float* cm_c2 = (const float*)d_in[14];
    const float* bo_w1 = (const float*)d_in[15];
    const float* bo_g  = (const float*)d_in[16];
    const float* bo_b  = (const float*)d_in[17];
    const float* bo_w2 = (const float*)d_in[18];
    float* out = (float*)d_out;

    k_zero<<<1, 128>>>();

    // compenv branch (shift-invariance collapse)
    k_stats6<<<512, 256>>>(x, 0);
    k_final6<<<1, 64>>>(ce_w1, ce_g, ce_b, 0, 0);
    k_E<<<2048, 256>>>(x, ce_w1, ce_w2);

    // merge determinant branch
    k_conv1<<<dim3(9, 9, 48), 128>>>(x, md_ct);
    k_conv2<<<dim3(8, 8, 48), 128>>>(md_c1);           // fused md stats
    k_final48<<<1, 64>>>(md_g, md_b, 0, 1, 524288.0);
    k_change<<<512, 256>>>(md_c2);

    // cell merge branch
    k_cm1<<<(BATCH*NC*HWo + 255)/256, 256>>>(x, cm_w1);
    k_stats48<<<dim3(48, 32), 256>>>(1);
    k_final48<<<1, 64>>>(cm_g, cm_b, 1, 2, 131072.0);
    k_convcm<<<dim3(5, 5, 96), 128>>>(cm_ct);
    k_convxm<<<dim3(4, 4, 24), 128>>>(cm_c2);

    // born + blend
    k_stats6<<<512, 256>>>(x, 1);
    k_final6<<<1, 64>>>(bo_w1, bo_g, bo_b, 1, 3);
    k_final<<<512, 256>>>(bo_w1, bo_w2, out);
}

// round 11
// speedup vs baseline: 1.5635x; 1.0617x over previous
#include <cuda_runtime.h>
#include <math.h>
#include <stdint.h>

#define BATCH 8
#define DCH 6
#define NC 48
#define HW 65536            // 256*256
#define H1 258
#define W1S 264
#define CH1SZ (H1*W1S)      // 68112
#define H3 130
#define W3S 132
#define CH3SZ (H3*W3S)      // 17160
#define HWo 16384           // 128*128
#define SS 36               // smem tile stride (floats), 16B-aligned rows

typedef unsigned long long u64;

// ---------------- scratch (static device memory; no allocations) ----------------
__device__ float g_E[BATCH*HW];                          // 2 MB
__device__ float g_h1[(size_t)BATCH*NC*CH1SZ];           // ~105 MB  tanh(conv1)
__device__ float g_h2[(size_t)BATCH*NC*HW];              // ~101 MB  tanh(conv2)
__device__ float g_cm1[(size_t)BATCH*NC*HWo];            // 25 MB    raw cm conv
__device__ float g_h3[(size_t)BATCH*NC*CH3SZ];           // 26 MB    tanh(conv cm_ct)
__device__ float g_xm[BATCH*DCH*HWo];                    // 3 MB
__device__ float g_chg[BATCH*HWo];                       // 0.5 MB

__device__ double g_S6[2][6];     // 0: x moments, 1: xm moments
__device__ double g_M6[2][21];
__device__ double g_S48[2][48];   // 0: h2, 1: cm1
__device__ double g_SS48[2][48];
__device__ float  g_scale[4][48]; // 0=ce,1=md,2=cm,3=bo
__device__ float  g_shift[4][48];

__device__ const int g_DX[8] = {0,1,1,1,0,-1,-1,-1};
__device__ const int g_DY[8] = {1,1,0,-1,-1,-1,0,1};

__device__ __forceinline__ void cp_async16(void* sdst, const void* gsrc) {
    unsigned s = (unsigned)__cvta_generic_to_shared(sdst);
    asm volatile("cp.async.ca.shared.global [%0], [%1], 16;\n" :: "r"(s), "l"(gsrc));
}
__device__ __forceinline__ void cp_async8(void* sdst, const void* gsrc) {
    unsigned s = (unsigned)__cvta_generic_to_shared(sdst);
    asm volatile("cp.async.ca.shared.global [%0], [%1], 8;\n" :: "r"(s), "l"(gsrc));
}
__device__ __forceinline__ void cp_commit() {
    asm volatile("cp.async.commit_group;\n");
}
__device__ __forceinline__ void cp_wait0() {
    asm volatile("cp.async.wait_group 0;\n");
}
// HW tanh (sm_75+). Used ONLY in the md/CHANGE branch (sigmoid-squashed).
__device__ __forceinline__ float tanha(float x) {
    float y; asm("tanh.approx.f32 %0, %1;" : "=f"(y) : "f"(x)); return y;
}
// packed f32x2 helpers (sm_103a FFMA2 path)
__device__ __forceinline__ u64 pk(float lo, float hi) {
    u64 r; asm("mov.b64 %0, {%1, %2};" : "=l"(r) : "f"(lo), "f"(hi)); return r;
}
__device__ __forceinline__ void fma2(u64& d, u64 a, u64 b) {
    asm("fma.rn.f32x2 %0, %1, %2, %0;" : "+l"(d) : "l"(a), "l"(b));
}
__device__ __forceinline__ float2 upk(u64 v) {
    float2 f; asm("mov.b64 {%0, %1}, %2;" : "=f"(f.x), "=f"(f.y) : "l"(v)); return f;
}

// ---------------- zero stats ----------------
__global__ void k_zero() {
    int t = threadIdx.x;
    if (t < 12) (&g_S6[0][0])[t] = 0.0;
    if (t < 42) (&g_M6[0][0])[t] = 0.0;
    if (t < 96) (&g_S48[0][0])[t] = 0.0;
    if (t < 96) (&g_SS48[0][0])[t] = 0.0;
}

// ---------------- 6-channel first/second moments (x or xm) ----------------
__global__ void k_stats6(const float* __restrict__ xin, int which) {
    const float* p = which ? (const float*)g_xm : xin;
    int HWl = which ? HWo : HW;
    double* S = g_S6[which];
    double* M = g_M6[which];
    int total = BATCH*HWl;
    double mu[6]; double mm[21];
#pragma unroll
    for (int d = 0; d < 6; d++) mu[d] = 0.0;
#pragma unroll
    for (int i = 0; i < 21; i++) mm[i] = 0.0;
    for (int idx = blockIdx.x*blockDim.x + threadIdx.x; idx < total;
         idx += gridDim.x*blockDim.x) {
        int b = idx / HWl; int q = idx - b*HWl;
        const float* base = p + (size_t)b*6*HWl + q;
        float v[6];
#pragma unroll
        for (int d = 0; d < 6; d++) v[d] = base[(size_t)d*HWl];
        int t = 0;
#pragma unroll
        for (int d = 0; d < 6; d++) {
            mu[d] += (double)v[d];
#pragma unroll
            for (int e = d; e < 6; e++) { mm[t] += (double)v[d]*(double)v[e]; t++; }
        }
    }
#pragma unroll
    for (int o = 16; o > 0; o >>= 1) {
#pragma unroll
        for (int d = 0; d < 6; d++)  mu[d] += __shfl_down_sync(0xffffffffu, mu[d], o);
#pragma unroll
        for (int i = 0; i < 21; i++) mm[i] += __shfl_down_sync(0xffffffffu, mm[i], o);
    }
    __shared__ double sS[6], sM[21];
    if (threadIdx.x < 6)  sS[threadIdx.x] = 0.0;
    if (threadIdx.x < 21) sM[threadIdx.x] = 0.0;
    __syncthreads();
    if ((threadIdx.x & 31) == 0) {
        for (int d = 0; d < 6; d++)  atomicAdd(&sS[d], mu[d]);
        for (int i = 0; i < 21; i++) atomicAdd(&sM[i], mm[i]);
    }
    __syncthreads();
    if (threadIdx.x < 6)  atomicAdd(&S[threadIdx.x], sS[threadIdx.x]);
    if (threadIdx.x < 21) atomicAdd(&M[threadIdx.x], sM[threadIdx.x]);
}

// ---------------- analytic BN for 1x1 convs (ce / bo) ----------------
__global__ void k_final6(const float* __restrict__ w1, const float* __restrict__ gg,
                         const float* __restrict__ bb, int which, int outi) {
    int c = threadIdx.x; if (c >= 48) return;
    double N = which ? (double)(BATCH*HWo) : (double)(BATCH*HW);
    const double* S = g_S6[which];
    const double* M = g_M6[which];
    double wl[6]; double m = 0.0;
    for (int d = 0; d < 6; d++) { wl[d] = (double)w1[c*6+d]; m += wl[d]*(S[d]/N); }
    double e2 = 0.0; int t = 0;
    for (int d = 0; d < 6; d++)
        for (int e = d; e < 6; e++) {
            double coef = (d == e) ? 1.0 : 2.0;
            e2 += coef*wl[d]*wl[e]*(M[t]/N); t++;
        }
    double var = e2 - m*m;
    if (var < 0.0) var = 0.0;
    double sc = (double)gg[c] / sqrt(var + 1e-5);
    g_scale[outi][c] = (float)sc;
    g_shift[outi][c] = (float)((double)bb[c] - sc*m);
}

// ---------------- per-channel sum/sumsq over 48-ch tensors (cm1) ----------------
__global__ void k_stats48(int which) {
    const float* p = which ? (const float*)g_cm1 : (const float*)g_h2;
    int HWl = which ? HWo : HW;
    int c = blockIdx.x;
    int total = BATCH*HWl;
    double s = 0.0, ss = 0.0;
    for (int idx = blockIdx.y*blockDim.x + threadIdx.x; idx < total;
         idx += gridDim.y*blockDim.x) {
        int b = idx / HWl; int q = idx - b*HWl;
        float v = p[((size_t)(b*NC + c))*HWl + q];
        s += (double)v; ss += (double)v*(double)v;
    }
#pragma unroll
    for (int o = 16; o > 0; o >>= 1) {
        s  += __shfl_down_sync(0xffffffffu, s, o);
        ss += __shfl_down_sync(0xffffffffu, ss, o);
    }
    __shared__ double sh[2];
    if (threadIdx.x == 0) { sh[0] = 0.0; sh[1] = 0.0; }
    __syncthreads();
    if ((threadIdx.x & 31) == 0) { atomicAdd(&sh[0], s); atomicAdd(&sh[1], ss); }
    __syncthreads();
    if (threadIdx.x == 0) {
        atomicAdd(&g_S48[which][c], sh[0]);
        atomicAdd(&g_SS48[which][c], sh[1]);
    }
}

__global__ void k_final48(const float* __restrict__ gg, const float* __restrict__ bb,
                          int which, int outi, double N) {
    int c = threadIdx.x; if (c >= 48) return;
    double mean = g_S48[which][c]/N;
    double var  = g_SS48[which][c]/N - mean*mean;
    if (var < 0.0) var = 0.0;
    double sc = (double)gg[c] / sqrt(var + 1e-5);
    g_scale[outi][c] = (float)sc;
    g_shift[outi][c] = (float)((double)bb[c] - sc*mean);
}

// ---------------- E map: fused 1x1 conv + analytic BN + tanh + 1x1 conv ----------------
__global__ void k_E(const float* __restrict__ x, const float* __restrict__ w1,
                    const float* __restrict__ w2) {
    __shared__ float sw1[288], sw2[48], ssc[48], ssh[48];
    int t = threadIdx.x;
    for (int i = t; i < 288; i += 256) sw1[i] = w1[i];
    if (t < 48) { sw2[t] = w2[t]; ssc[t] = g_scale[0][t]; ssh[t] = g_shift[0][t]; }
    __syncthreads();
    int idx = blockIdx.x*blockDim.x + t;   // 2048*256 = 524288 exactly
    int b = idx >> 16; int q = idx & 65535;
    const float* base = x + (size_t)b*6*HW + q;
    float v0 = base[0], v1 = base[HW], v2 = base[2*HW];
    float v3 = base[3*HW], v4 = base[4*HW], v5 = base[5*HW];
    float sum = 0.f;
#pragma unroll 8
    for (int c = 0; c < 48; c++) {
        const float* w = sw1 + c*6;
        float u = w[0]*v0 + w[1]*v1 + w[2]*v2 + w[3]*v3 + w[4]*v4 + w[5]*v5;
        sum += sw2[c]*tanha(ssc[c]*u + ssh[c]);
    }
    g_E[idx] = sum;
}

// ---------------- conv1: te(10ch, virtual) -> 48, k3, pad2, out 258x258, tanh ----------------
__global__ void __launch_bounds__(128) k_conv1(const float* __restrict__ x,
                                               const float* __restrict__ wct) {
    __shared__ float s_in[5][34*SS];
    __shared__ float2 s_wp[720];          // [oc8][cg10][kh3][tap3] duplicated
    int b = blockIdx.z / 6, ocg = blockIdx.z % 6, oc0 = ocg*8;
    int r0 = blockIdx.y*32, c0 = blockIdx.x*32;
    for (int i = threadIdx.x; i < 720; i += 128) {
        float v = wct[(size_t)oc0*90 + i];
        s_wp[i] = make_float2(v, v);
    }
    u64 accp[8][2][2];
#pragma unroll
    for (int a = 0; a < 8; a++)
#pragma unroll
        for (int r = 0; r < 2; r++)
#pragma unroll
            for (int j = 0; j < 2; j++) accp[a][r][j] = 0ull;
    int tx = threadIdx.x & 7, ty = threadIdx.x >> 3;   // tx 0..7, ty 0..15
    const float* Eb = g_E + (size_t)b*HW;
    for (int ch0 = 0; ch0 < 10; ch0 += 5) {
        __syncthreads();
        for (int i = threadIdx.x; i < 5*1156; i += 128) {
            int c = i / 1156; int r2 = i - c*1156;
            int rr = r2 / 34, cc = r2 - rr*34;
            int hi = r0 - 2 + rr, wi = c0 - 2 + cc;
            float v = 0.f;
            int cg = ch0 + c;
            if ((unsigned)hi < 256u && (unsigned)wi < 256u) {
                if (cg < 2) v = x[((size_t)(b*6 + cg))*HW + hi*256 + wi];
                else {
                    int k = cg - 2;
                    int hh = (hi + g_DY[k]) & 255;
                    int wz = (wi - g_DX[k]) & 255;
                    v = Eb[hh*256 + wz];
                }
            }
            s_in[c][rr*SS + cc] = v;
        }
        __syncthreads();
#pragma unroll
        for (int c = 0; c < 5; c++) {
            int cg = ch0 + c;
#pragma unroll
            for (int kh = 0; kh < 3; kh++) {
                const float* pa = &s_in[c][(ty + kh)*SS + 4*tx];
                const float* pb = &s_in[c][(ty + 16 + kh)*SS + 4*tx];
                float4 av = *(const float4*)pa; float2 av2 = *(const float2*)(pa + 4);
                float4 bv = *(const float4*)pb; float2 bv2 = *(const float2*)(pb + 4);
                u64 ap0 = pk(av.x,av.y), ap1 = pk(av.y,av.z), ap2 = pk(av.z,av.w),
                    ap3 = pk(av.w,av2.x), ap4 = pk(av2.x,av2.y);
                u64 bp0 = pk(bv.x,bv.y), bp1 = pk(bv.y,bv.z), bp2 = pk(bv.z,bv.w),
                    bp3 = pk(bv.w,bv2.x), bp4 = pk(bv2.x,bv2.y);
#pragma unroll
                for (int oc = 0; oc < 8; oc++) {
                    const u64* wq = (const u64*)s_wp + (oc*10 + cg)*9 + kh*3;
                    u64 w0 = wq[0], w1v = wq[1], w2v = wq[2];
                    fma2(accp[oc][0][0], w0, ap0); fma2(accp[oc][0][0], w1v, ap1); fma2(accp[oc][0][0], w2v, ap2);
                    fma2(accp[oc][0][1], w0, ap2); fma2(accp[oc][0][1], w1v, ap3); fma2(accp[oc][0][1], w2v, ap4);
                    fma2(accp[oc][1][0], w0, bp0); fma2(accp[oc][1][0], w1v, bp1); fma2(accp[oc][1][0], w2v, bp2);
                    fma2(accp[oc][1][1], w0, bp2); fma2(accp[oc][1][1], w1v, bp3); fma2(accp[oc][1][1], w2v, bp4);
                }
            }
        }
    }
#pragma unroll
    for (int oc = 0; oc < 8; oc++) {
        size_t base = ((size_t)(b*NC + oc0 + oc))*CH1SZ;
#pragma unroll
        for (int rsel = 0; rsel < 2; rsel++) {
            int orow = r0 + ty + rsel*16;
            if (orow >= H1) continue;
            float2 lo = upk(accp[oc][rsel][0]);
            float2 hi = upk(accp[oc][rsel][1]);
            float vv[4] = {lo.x, lo.y, hi.x, hi.y};
#pragma unroll
            for (int jj = 0; jj < 4; jj++) {
                int ocol = c0 + 4*tx + jj;
                if (ocol < H1)
                    g_h1[base + (size_t)orow*W1S + ocol] = tanha(vv[jj]);
            }
        }
    }
}

// ---------------- conv2: 48 -> 48, k3, 256x256 out, tanh (dominant kernel) ----------------
// FFMA2 path: 8 oc/block, 16B cp.async double-buffered, duplicated float2 weights,
// fused per-channel sum/sumsq stats (md BN).
#define C2NCH 16
__global__ void __launch_bounds__(128) k_conv2(const float* __restrict__ wc1) {
    __shared__ float s_in[2][3][34*SS];   // 29376 B
    __shared__ float2 s_wp[8*432];        // 27648 B  [oc][ic][kh][tap] duplicated
    __shared__ float s_red[8][4][2];
    int b = blockIdx.z / 6, ocg = blockIdx.z % 6, oc0 = ocg*8;
    int r0 = blockIdx.y*32, c0 = blockIdx.x*32;
    for (int i = threadIdx.x; i < 8*432; i += 128) {
        float v = wc1[(size_t)oc0*432 + i];
        s_wp[i] = make_float2(v, v);
    }
    u64 accp[8][2][2];
#pragma unroll
    for (int a = 0; a < 8; a++)
#pragma unroll
        for (int r = 0; r < 2; r++)
#pragma unroll
            for (int j = 0; j < 2; j++) accp[a][r][j] = 0ull;
    int tx = threadIdx.x & 7, ty = threadIdx.x >> 3;
    const float* h1b = g_h1 + (size_t)b*NC*CH1SZ + (size_t)r0*W1S + c0;

    // vectorized tile fill: 3 ch x 34 rows x (8 x 16B + 1 x 8B) = 918 ops
    {
        for (int i = threadIdx.x; i < 918; i += 128) {
            int c = i/306, rem = i - c*306, row = rem/9, seg = rem - row*9;
            const float* src = h1b + (size_t)c*CH1SZ + (size_t)row*W1S + seg*4;
            float* dst = &s_in[0][c][row*SS + seg*4];
            if (seg < 8) cp_async16(dst, src); else cp_async8(dst, src);
        }
        cp_commit();
    }
    for (int k = 0; k < C2NCH; k++) {
        cp_wait0();
        __syncthreads();
        if (k + 1 < C2NCH) {
            const float* src0 = h1b + (size_t)(k+1)*3*CH1SZ;
            float (*dst0)[34*SS] = s_in[(k+1) & 1];
            for (int i = threadIdx.x; i < 918; i += 128) {
                int c = i/306, rem = i - c*306, row = rem/9, seg = rem - row*9;
                const float* src = src0 + (size_t)c*CH1SZ + (size_t)row*W1S + seg*4;
                float* dst = &dst0[c][row*SS + seg*4];
                if (seg < 8) cp_async16(dst, src); else cp_async8(dst, src);
            }
            cp_commit();
        }
        const float (*buf)[34*SS] = s_in[k & 1];
#pragma unroll
        for (int c = 0; c < 3; c++) {
            int cg = k*3 + c;
#pragma unroll
            for (int kh = 0; kh < 3; kh++) {
                const float* pa = &buf[c][(ty + kh)*SS + 4*tx];
                const float* pb = &buf[c][(ty + 16 + kh)*SS + 4*tx];
                float4 av = *(const float4*)pa; float2 av2 = *(const float2*)(pa + 4);
                float4 bv = *(const float4*)pb; float2 bv2 = *(const float2*)(pb + 4);
                u64 ap0 = pk(av.x,av.y), ap1 = pk(av.y,av.z), ap2 = pk(av.z,av.w),
                    ap3 = pk(av.w,av2.x), ap4 = pk(av2.x,av2.y);
                u64 bp0 = pk(bv.x,bv.y), bp1 = pk(bv.y,bv.z), bp2 = pk(bv.z,bv.w),
                    bp3 = pk(bv.w,bv2.x), bp4 = pk(bv2.x,bv2.y);
#pragma unroll
                for (int oc = 0; oc < 8; oc++) {
                    const u64* wq = (const u64*)s_wp + (oc*48 + cg)*9 + kh*3;
                    u64 w0 = wq[0], w1v = wq[1], w2v = wq[2];
                    fma2(accp[oc][0][0], w0, ap0); fma2(accp[oc][0][0], w1v, ap1); fma2(accp[oc][0][0], w2v, ap2);
                    fma2(accp[oc][0][1], w0, ap2); fma2(accp[oc][0][1], w1v, ap3); fma2(accp[oc][0][1], w2v, ap4);
                    fma2(accp[oc][1][0], w0, bp0); fma2(accp[oc][1][0], w1v, bp1); fma2(accp[oc][1][0], w2v, bp2);
                    fma2(accp[oc][1][1], w0, bp2); fma2(accp[oc][1][1], w1v, bp3); fma2(accp[oc][1][1], w2v, bp4);
                }
            }
        }
    }
    // epilogue: tanh, store, fused per-oc stats
    int lane = threadIdx.x & 31, wrp = threadIdx.x >> 5;
    float osum[8], osq[8];
#pragma unroll
    for (int oc = 0; oc < 8; oc++) {
        size_t base = ((size_t)(b*NC + oc0 + oc))*HW;
        float s = 0.f, sq = 0.f;
#pragma unroll
        for (int rsel = 0; rsel < 2; rsel++) {
            int orow = r0 + ty + rsel*16;
            float2 lo = upk(accp[oc][rsel][0]);
            float2 hi = upk(accp[oc][rsel][1]);
            float vv[4] = {lo.x, lo.y, hi.x, hi.y};
#pragma unroll
            for (int jj = 0; jj < 4; jj++) {
                float tv = tanha(vv[jj]);
                g_h2[base + (size_t)orow*256 + (c0 + 4*tx + jj)] = tv;
                s += tv; sq += tv*tv;
            }
        }
        osum[oc] = s; osq[oc] = sq;
    }
#pragma unroll
    for (int oc = 0; oc < 8; oc++) {
#pragma unroll
        for (int o = 16; o > 0; o >>= 1) {
            osum[oc] += __shfl_down_sync(0xffffffffu, osum[oc], o);
            osq[oc]  += __shfl_down_sync(0xffffffffu, osq[oc], o);
        }
        if (lane == 0) { s_red[oc][wrp][0] = osum[oc]; s_red[oc][wrp][1] = osq[oc]; }
    }
    __syncthreads();
    if (threadIdx.x < 16) {
        int oc = threadIdx.x >> 1, sel = threadIdx.x & 1;
        float v = s_red[oc][0][sel] + s_red[oc][1][sel] + s_red[oc][2][sel] + s_red[oc][3][sel];
        if (sel) atomicAdd(&g_SS48[0][oc0 + oc], (double)v);
        else     atomicAdd(&g_S48[0][oc0 + oc], (double)v);
    }
}

// ---------------- CHANGE: bn+tanh(h2) -> k2 s2 conv -> sigmoid ----------------
__global__ void k_change(const float* __restrict__ w2) {
    __shared__ float ssc[48], ssh[48], sw[192];
    int t = threadIdx.x;
    if (t < 48)  { ssc[t] = g_scale[1][t]; ssh[t] = g_shift[1][t]; }
    if (t < 192) sw[t] = w2[t];
    __syncthreads();
    int idx = blockIdx.x*256 + t;   // 512*256 = 131072 exactly
    int b = idx >> 14; int q = idx & 16383;
    int i = q >> 7, j = q & 127;
    const float* h2b = g_h2 + ((size_t)b*NC)*HW + (size_t)(2*i)*256 + 2*j;
    float acc = 0.f;
#pragma unroll 4
    for (int c = 0; c < 48; c++) {
        const float* p = h2b + (size_t)c*HW;
        float sc = ssc[c], sh = ssh[c];
        acc += sw[c*4+0]*tanha(sc*p[0]   + sh);
        acc += sw[c*4+1]*tanha(sc*p[1]   + sh);
        acc += sw[c*4+2]*tanha(sc*p[256] + sh);
        acc += sw[c*4+3]*tanha(sc*p[257] + sh);
    }
    g_chg[idx] = 1.f/(1.f + expf(-acc));
}

// ---------------- cm1: grouped k2 s2 conv (D->NC, g3) ----------------
__global__ void k_cm1(const float* __restrict__ x, const float* __restrict__ w) {
    int idx = blockIdx.x*blockDim.x + threadIdx.x;
    if (idx >= BATCH*NC*HWo) return;
    int q = idx & 16383; int co = idx >> 14;
    int o = co % 48; int b = co / 48;
    int i = q >> 7, j = q & 127;
    int ic0 = (o >> 4)*2;
    const float* xb = x + ((size_t)(b*6 + ic0))*HW + (size_t)(2*i)*256 + 2*j;
    const float* wp = w + o*8;
    float acc = xb[0]*wp[0] + xb[1]*wp[1] + xb[256]*wp[2] + xb[257]*wp[3]
              + xb[HW]*wp[4] + xb[HW+1]*wp[5] + xb[HW+256]*wp[6] + xb[HW+257]*wp[7];
    g_cm1[idx] = acc;
}

// ---------------- conv cm_ct: bn+tanh(cm1) -> k3 pad2 grouped conv -> tanh, 130x130 ----------------
__global__ void __launch_bounds__(128) k_convcm(const float* __restrict__ wct) {
    __shared__ float s_in[8][34*SS];
    __shared__ float2 s_wp[576];          // [oc4][ic16][kh3][tap3] duplicated
    int b = blockIdx.z / 12, ocg = blockIdx.z % 12, oc0 = ocg*4;
    int icb = (oc0 >> 4)*16;
    int r0 = blockIdx.y*32, c0 = blockIdx.x*32;
    for (int i = threadIdx.x; i < 576; i += 128) {
        float v = wct[(size_t)oc0*144 + i];
        s_wp[i] = make_float2(v, v);
    }
    u64 accp[4][2][2];
#pragma unroll
    for (int a = 0; a < 4; a++)
#pragma unroll
        for (int r = 0; r < 2; r++)
#pragma unroll
            for (int j = 0; j < 2; j++) accp[a][r][j] = 0ull;
    int tx = threadIdx.x & 7, ty = threadIdx.x >> 3;
    for (int ch0 = 0; ch0 < 16; ch0 += 8) {
        __syncthreads();
        for (int i = threadIdx.x; i < 8*1156; i += 128) {
            int c = i / 1156; int r2 = i - c*1156;
            int rr = r2 / 34, cc = r2 - rr*34;
            int hi = r0 - 2 + rr, wi = c0 - 2 + cc;
            float v = 0.f;
            int cg = icb + ch0 + c;
            if ((unsigned)hi < 128u && (unsigned)wi < 128u) {
                float raw = g_cm1[((size_t)(b*NC + cg))*HWo + hi*128 + wi];
                v = tanhf(g_scale[2][cg]*raw + g_shift[2][cg]);
            }
            s_in[c][rr*SS + cc] = v;
        }
        __syncthreads();
#pragma unroll
        for (int c = 0; c < 8; c++) {
#pragma unroll
            for (int kh = 0; kh < 3; kh++) {
                const float* pa = &s_in[c][(ty + kh)*SS + 4*tx];
                const float* pb = &s_in[c][(ty + 16 + kh)*SS + 4*tx];
                float4 av = *(const float4*)pa; float2 av2 = *(const float2*)(pa + 4);
                float4 bv = *(const float4*)pb; float2 bv2 = *(const float2*)(pb + 4);
                u64 ap0 = pk(av.x,av.y), ap1 = pk(av.y,av.z), ap2 = pk(av.z,av.w),
                    ap3 = pk(av.w,av2.x), ap4 = pk(av2.x,av2.y);
                u64 bp0 = pk(bv.x,bv.y), bp1 = pk(bv.y,bv.z), bp2 = pk(bv.z,bv.w),
                    bp3 = pk(bv.w,bv2.x), bp4 = pk(bv2.x,bv2.y);
#pragma unroll
                for (int oc = 0; oc < 4; oc++) {
                    const u64* wq = (const u64*)s_wp + (oc*16 + ch0 + c)*9 + kh*3;
                    u64 w0 = wq[0], w1v = wq[1], w2v = wq[2];
                    fma2(accp[oc][0][0], w0, ap0); fma2(accp[oc][0][0], w1v, ap1); fma2(accp[oc][0][0], w2v, ap2);
                    fma2(accp[oc][0][1], w0, ap2); fma2(accp[oc][0][1], w1v, ap3); fma2(accp[oc][0][1], w2v, ap4);
                    fma2(accp[oc][1][0], w0, bp0); fma2(accp[oc][1][0], w1v, bp1); fma2(accp[oc][1][0], w2v, bp2);
                    fma2(accp[oc][1][1], w0, bp2); fma2(accp[oc][1][1], w1v, bp3); fma2(accp[oc][1][1], w2v, bp4);
                }
            }
        }
    }
#pragma unroll
    for (int oc = 0; oc < 4; oc++) {
        size_t base = ((size_t)(b*NC + oc0 + oc))*CH3SZ;
#pragma unroll
        for (int rsel = 0; rsel < 2; rsel++) {
            int orow = r0 + ty + rsel*16;
            if (orow >= H3) continue;
            float2 lo = upk(accp[oc][rsel][0]);
            float2 hi = upk(accp[oc][rsel][1]);
            float vv[4] = {lo.x, lo.y, hi.x, hi.y};
#pragma unroll
            for (int jj = 0; jj < 4; jj++) {
                int ocol = c0 + 4*tx + jj;
                if (ocol < H3)
                    g_h3[base + (size_t)orow*W3S + ocol] = tanhf(vv[jj]);
            }
        }
    }
}

// ---------------- xm: k3 grouped conv (NC->D, g3), out 128x128, tanh ----------------
__global__ void __launch_bounds__(128) k_convxm(const float* __restrict__ wc2) {
    __shared__ float s_in[8][34*SS];
    __shared__ float2 s_wp[288];          // [oc2][ic16][kh3][tap3] duplicated
    int b = blockIdx.z / 3, g = blockIdx.z % 3;
    int r0 = blockIdx.y*32, c0 = blockIdx.x*32;
    for (int i = threadIdx.x; i < 288; i += 128) {
        float v = wc2[(size_t)g*288 + i];
        s_wp[i] = make_float2(v, v);
    }
    u64 accp[2][2][2];
#pragma unroll
    for (int a = 0; a < 2; a++)
#pragma unroll
        for (int r = 0; r < 2; r++)
#pragma unroll
            for (int j = 0; j < 2; j++) accp[a][r][j] = 0ull;
    int tx = threadIdx.x & 7, ty = threadIdx.x >> 3;
    for (int ch0 = 0; ch0 < 16; ch0 += 8) {
        __syncthreads();
        for (int i = threadIdx.x; i < 8*1156; i += 128) {
            int c = i / 1156; int r2 = i - c*1156;
            int rr = r2 / 34, cc = r2 - rr*34;
            s_in[c][rr*SS + cc] = g_h3[((size_t)(b*NC + g*16 + ch0 + c))*CH3SZ
                                   + (size_t)(r0 + rr)*W3S + (c0 + cc)];
        }
        __syncthreads();
#pragma unroll
        for (int c = 0; c < 8; c++) {
#pragma unroll
            for (int kh = 0; kh < 3; kh++) {
                const float* pa = &s_in[c][(ty + kh)*SS + 4*tx];
                const float* pb = &s_in[c][(ty + 16 + kh)*SS + 4*tx];
                float4 av = *(const float4*)pa; float2 av2 = *(const float2*)(pa + 4);
                float4 bv = *(const float4*)pb; float2 bv2 = *(const float2*)(pb + 4);
                u64 ap0 = pk(av.x,av.y), ap1 = pk(av.y,av.z), ap2 = pk(av.z,av.w),
                    ap3 = pk(av.w,av2.x), ap4 = pk(av2.x,av2.y);
                u64 bp0 = pk(bv.x,bv.y), bp1 = pk(bv.y,bv.z), bp2 = pk(bv.z,bv.w),
                    bp3 = pk(bv.w,bv2.x), bp4 = pk(bv2.x,bv2.y);
#pragma unroll
                for (int oc = 0; oc < 2; oc++) {
                    const u64* wq = (const u64*)s_wp + (oc*16 + ch0 + c)*9 + kh*3;
                    u64 w0 = wq[0], w1v = wq[1], w2v = wq[2];
                    fma2(accp[oc][0][0], w0, ap0); fma2(accp[oc][0][0], w1v, ap1); fma2(accp[oc][0][0], w2v, ap2);
                    fma2(accp[oc][0][1], w0, ap2); fma2(accp[oc][0][1], w1v, ap3); fma2(accp[oc][0][1], w2v, ap4);
                    fma2(accp[oc][1][0], w0, bp0); fma2(accp[oc][1][0], w1v, bp1); fma2(accp[oc][1][0], w2v, bp2);
                    fma2(accp[oc][1][1], w0, bp2); fma2(accp[oc][1][1], w1v, bp3); fma2(accp[oc][1][1], w2v, bp4);
                }
            }
        }
    }
#pragma unroll
    for (int oc = 0; oc < 2; oc++) {
        size_t base = ((size_t)(b*6 + g*2 + oc))*HWo;
#pragma unroll
        for (int rsel = 0; rsel < 2; rsel++) {
            int orow = r0 + ty + rsel*16;
            float2 lo = upk(accp[oc][rsel][0]);
            float2 hi = upk(accp[oc][rsel][1]);
            float vv[4] = {lo.x, lo.y, hi.x, hi.y};
#pragma unroll
            for (int jj = 0; jj < 4; jj++)
                g_xm[base + (size_t)orow*128 + (c0 + 4*tx + jj)] = tanhf(vv[jj]);
        }
    }
}

// ---------------- final: born (fused 1x1/BN/tanh/1x1) + blend + partial sigmoid ----------------
__global__ void k_final(const float* __restrict__ w1, const float* __restrict__ w2,
                        float* __restrict__ out) {
    __shared__ float sw1[288], sw2[288], ssc[48], ssh[48];
    int t = threadIdx.x;
    for (int i = t; i < 288; i += 256) { sw1[i] = w1[i]; sw2[i] = w2[i]; }
    if (t < 48)  { ssc[t] = g_scale[3][t]; ssh[t] = g_shift[3][t]; }
    __syncthreads();
    int idx = blockIdx.x*256 + t;    // 512*256 = 131072 exactly
    int b = idx >> 14; int q = idx & 16383;
    const float* xb = g_xm + (size_t)b*6*HWo + q;
    float v[6];
#pragma unroll
    for (int d = 0; d < 6; d++) v[d] = xb[(size_t)d*HWo];
    float bo[6] = {0.f,0.f,0.f,0.f,0.f,0.f};
#pragma unroll 8
    for (int c = 0; c < 48; c++) {
        const float* w = sw1 + c*6;
        float u = w[0]*v[0] + w[1]*v[1] + w[2]*v[2] + w[3]*v[3] + w[4]*v[4] + w[5]*v[5];
        float tv = tanhf(ssc[c]*u + ssh[c]);
#pragma unroll
        for (int d = 0; d < 6; d++) bo[d] += sw2[d*48 + c]*tv;
    }
    float ch = g_chg[idx];
#pragma unroll
    for (int d = 0; d < 6; d++) {
        float r = v[d]*(1.f - ch) + ch*bo[d];
        if (d < 3) r = 1.f/(1.f + expf(-r));
        out[((size_t)(b*6 + d))*HWo + q] = r;
    }
}

// ---------------- launch ----------------
extern "C" void kernel_launch(void* const* d_in, const int* in_sizes, int n_in,
                              void* d_out, int out_size) {
    (void)in_sizes; (void)n_in; (void)out_size;
    const float* x     = (const float*)d_in[0];
    const float* ce_w1 = (const float*)d_in[1];
    const float* ce_g  = (const float*)d_in[2];
    const float* ce_b  = (const float*)d_in[3];
    const float* ce_w2 = (const float*)d_in[4];
    const float* md_ct = (const float*)d_in[5];
    const float* md_c1 = (const float*)d_in[6];
    const float* md_g  = (const float*)d_in[7];
    const float* md_b  = (const float*)d_in[8];
    const float* md_c2 = (const float*)d_in[9];
    const float* cm_w1 = (const float*)d_in[10];
    const float* cm_g  = (const float*)d_in[11];
    const float* cm_b  = (const float*)d_in[12];
    const float* cm_ct = (const float*)d_in[13];
    const float* cm_c2 = (const float*)d_in[14];
    const float* bo_w1 = (const float*)d_in[15];
    const float* bo_g  = (const float*)d_in[16];
    const float* bo_b  = (const float*)d_in[17];
    const float* bo_w2 = (const float*)d_in[18];
    float* out = (float*)d_out;

    k_zero<<<1, 128>>>();

    // compenv branch (shift-invariance collapse)
    k_stats6<<<512, 256>>>(x, 0);
    k_final6<<<1, 64>>>(ce_w1, ce_g, ce_b, 0, 0);
    k_E<<<2048, 256>>>(x, ce_w1, ce_w2);

    // merge determinant branch
    k_conv1<<<dim3(9, 9, 48), 128>>>(x, md_ct);
    k_conv2<<<dim3(8, 8, 48), 128>>>(md_c1);           // fused md stats
    k_final48<<<1, 64>>>(md_g, md_b, 0, 1, 524288.0);
    k_change<<<512, 256>>>(md_c2);

    // cell merge branch
    k_cm1<<<(BATCH*NC*HWo + 255)/256, 256>>>(x, cm_w1);
    k_stats48<<<dim3(48, 32), 256>>>(1);
    k_final48<<<1, 64>>>(cm_g, cm_b, 1, 2, 131072.0);
    k_convcm<<<dim3(5, 5, 96), 128>>>(cm_ct);
    k_convxm<<<dim3(4, 4, 24), 128>>>(cm_c2);

    // born + blend
    k_stats6<<<512, 256>>>(x, 1);
    k_final6<<<1, 64>>>(bo_w1, bo_g, bo_b, 1, 3);
    k_final<<<512, 256>>>(bo_w1, bo_w2, out);
}